// round 3
// baseline (speedup 1.0000x reference)
#include <cuda_runtime.h>
#include <cuda_bf16.h>
#include <math.h>

#define Bb  2
#define NN  8192
#define CA  128
#define CS  384
#define CZ  16
#define HH  4
#define DD  32
#define NQ  32
#define NK  128
#define NB  3
#define WW  256
#define HID 256
#define TT  (Bb*NN)          /* 16384 tokens */
#define ROWS 2097152         /* B*W*NQ*NK */

typedef unsigned long long ull;

// ---------------- scratch (device globals; no allocation allowed) ----------------
__device__ float g_sln [(size_t)TT*CS];
__device__ float g_gates[NB*6][(size_t)TT*CA];   // per blk: 0=adaln_sig 1=adaln_shift 2=sgate 3=t_sig 4=t_shift 5=t_sgate
__device__ float g_biasbuf[(size_t)NB*HH*ROWS];  // [blk][h][row]
__device__ float g_aln[(size_t)TT*CA];
__device__ float g_tln[(size_t)TT*CA];
__device__ float g_qh [(size_t)TT*CA];
__device__ float g_kh [(size_t)TT*CA];
__device__ float g_vh [(size_t)TT*CA];
__device__ float g_gh [(size_t)TT*CA];
__device__ float g_att[(size_t)TT*CA];
__device__ float g_ao [(size_t)TT*CA];
__device__ float g_a  [(size_t)TT*CA];
__device__ float g_hid[(size_t)2*TT*HID];        // ha | hb

__device__ __forceinline__ float sigm(float x){ return 1.f/(1.f+__expf(-x)); }

// reduce (sum, sumsq) across a 128-thread block
__device__ __forceinline__ void blockReduce2_128(float& s, float& q){
    __shared__ float sb[8];
    #pragma unroll
    for (int o=16;o;o>>=1){
        s += __shfl_xor_sync(0xffffffffu, s, o);
        q += __shfl_xor_sync(0xffffffffu, q, o);
    }
    int wid = threadIdx.x>>5;
    if ((threadIdx.x&31)==0){ sb[wid*2]=s; sb[wid*2+1]=q; }
    __syncthreads();
    s = sb[0]+sb[2]+sb[4]+sb[6];
    q = sb[1]+sb[3]+sb[5]+sb[7];
}

// ---------------- K1: layernorm of s (once) ----------------
__global__ void sln_kernel(const float* __restrict__ s){
    int t = blockIdx.x, tid = threadIdx.x;
    const float* row = s + (size_t)t*CS;
    float v0=row[tid], v1=row[tid+128], v2=row[tid+256];
    float su=v0+v1+v2, sq=v0*v0+v1*v1+v2*v2;
    blockReduce2_128(su,sq);
    float mean = su*(1.f/CS);
    float var  = sq*(1.f/CS) - mean*mean;
    float inv  = rsqrtf(var + 1e-5f);
    float* o = g_sln + (size_t)t*CS;
    o[tid]=(v0-mean)*inv; o[tid+128]=(v1-mean)*inv; o[tid+256]=(v2-mean)*inv;
}

// ---------------- K3: pair bias for all 3 blocks (once; reads p a single time) ----------------
__global__ void bias_kernel(const float* __restrict__ p, const float* __restrict__ lnz_w,
                            const float* __restrict__ lnz_b, const float* __restrict__ wb){
    __shared__ float s_w[NB*CZ], s_b[NB*CZ], s_wb[NB*CZ*HH];
    int tid = threadIdx.x;
    if (tid < NB*CZ){ s_w[tid]=lnz_w[tid]; s_b[tid]=lnz_b[tid]; }
    if (tid < NB*CZ*HH) s_wb[tid]=wb[tid];
    __syncthreads();
    size_t r = (size_t)blockIdx.x*blockDim.x + tid;
    if (r >= (size_t)ROWS) return;
    const float4* p4 = (const float4*)(p + r*CZ);
    float z[16];
    float4 q0=p4[0], q1=p4[1], q2=p4[2], q3=p4[3];
    z[0]=q0.x; z[1]=q0.y; z[2]=q0.z; z[3]=q0.w;
    z[4]=q1.x; z[5]=q1.y; z[6]=q1.z; z[7]=q1.w;
    z[8]=q2.x; z[9]=q2.y; z[10]=q2.z; z[11]=q2.w;
    z[12]=q3.x; z[13]=q3.y; z[14]=q3.z; z[15]=q3.w;
    float su=0, sq=0;
    #pragma unroll
    for (int c=0;c<16;c++){ su+=z[c]; sq+=z[c]*z[c]; }
    float mean=su*(1.f/16.f), var=sq*(1.f/16.f)-mean*mean;
    float inv=rsqrtf(var+1e-5f);
    #pragma unroll
    for (int c=0;c<16;c++) z[c]=(z[c]-mean)*inv;
    #pragma unroll
    for (int i=0;i<NB;i++){
        float o0=0,o1=0,o2=0,o3=0;
        #pragma unroll
        for (int c=0;c<16;c++){
            float zz = z[c]*s_w[i*16+c] + s_b[i*16+c];
            const float* w4 = &s_wb[(i*16+c)*4];
            o0 += zz*w4[0]; o1 += zz*w4[1]; o2 += zz*w4[2]; o3 += zz*w4[3];
        }
        size_t base = ((size_t)i*HH)*ROWS + r;
        g_biasbuf[base]        = o0;
        g_biasbuf[base+ROWS]   = o1;
        g_biasbuf[base+2*(size_t)ROWS] = o2;
        g_biasbuf[base+3*(size_t)ROWS] = o3;
    }
}

// ---------------- K4: LN(a) + both modulations (per block) ----------------
__global__ void lnmod_kernel(const float* __restrict__ a, int blk){
    int t = blockIdx.x, c = threadIdx.x;
    float x = a[(size_t)t*CA + c];
    float su=x, sq=x*x;
    blockReduce2_128(su,sq);
    float mean=su*(1.f/CA), var=sq*(1.f/CA)-mean*mean;
    float xn=(x-mean)*rsqrtf(var+1e-5f);
    size_t o=(size_t)t*CA+c;
    g_aln[o] = g_gates[blk*6+0][o]*xn + g_gates[blk*6+1][o];
    g_tln[o] = g_gates[blk*6+3][o]*xn + g_gates[blk*6+4][o];
}

// ---------------- GEMM: C[M,N] = A[M,K] @ B[K,N] + epilogue, packed f32x2 math ----------------
// BM=128, BN=64, BK=16, 256 threads, micro-tile 8m x 4n per thread.
// Accumulators paired along m (FFMA2): A pairs free from consecutive-m smem loads;
// B is stored duplicated in smem so b pairs are (b[n], b[n]).
// A2 != null: A_eff = silu(A)*A2 (GLU input fusion).
// epilogue: +bias[n]; sigmoid for n>=sigStart; *= mulp[m,n]; += addp[m,n]
__global__ __launch_bounds__(256) void gemm_kernel(
        const float* __restrict__ A, const float* __restrict__ A2,
        const float* __restrict__ Bm, const float* __restrict__ bias,
        const float* __restrict__ mulp, const float* __restrict__ addp,
        float* __restrict__ C, int M, int N, int K, int sigStart){
    __shared__ float As [16][128];   // [k][m]
    __shared__ float Bs2[16][128];   // [k][2n] duplicated
    int m0 = blockIdx.x*128, n0 = blockIdx.y*64;
    int tid = threadIdx.x;
    int ar = tid>>2, aq = tid&3;      // A load: rows ar, ar+64; k-group aq
    int br = tid>>4, bq = tid&15;     // B load: k row br, float4 col group bq
    int tr = tid>>4, tc = tid&15;     // compute: 8m x 4n micro-tile
    ull acc[4][4] = {};               // pairs over m
    const int nit = K>>4;

    const float* A0p = A + (size_t)(m0+ar)*K + aq*4;
    const float* A1p = A + (size_t)(m0+ar+64)*K + aq*4;
    const float* G0p = A2 ? A2 + (size_t)(m0+ar)*K + aq*4 : (const float*)0;
    const float* G1p = A2 ? A2 + (size_t)(m0+ar+64)*K + aq*4 : (const float*)0;
    const float* Bp  = Bm + (size_t)br*N + n0 + bq*4;

    float4 pa0, pa1, pg0, pg1, pb;
    pg0 = make_float4(0.f,0.f,0.f,0.f); pg1 = pg0;
    // prefetch iter 0
    pa0 = *(const float4*)(A0p);
    pa1 = *(const float4*)(A1p);
    if (A2){ pg0 = *(const float4*)(G0p); pg1 = *(const float4*)(G1p); }
    pb  = *(const float4*)(Bp);

    for (int it=0;;){
        // store prefetched tile to smem
        {
            float4 v0 = pa0, v1 = pa1;
            if (A2){
                v0.x = v0.x*sigm(v0.x)*pg0.x; v0.y = v0.y*sigm(v0.y)*pg0.y;
                v0.z = v0.z*sigm(v0.z)*pg0.z; v0.w = v0.w*sigm(v0.w)*pg0.w;
                v1.x = v1.x*sigm(v1.x)*pg1.x; v1.y = v1.y*sigm(v1.y)*pg1.y;
                v1.z = v1.z*sigm(v1.z)*pg1.z; v1.w = v1.w*sigm(v1.w)*pg1.w;
            }
            As[aq*4+0][ar]=v0.x; As[aq*4+1][ar]=v0.y; As[aq*4+2][ar]=v0.z; As[aq*4+3][ar]=v0.w;
            As[aq*4+0][ar+64]=v1.x; As[aq*4+1][ar+64]=v1.y; As[aq*4+2][ar+64]=v1.z; As[aq*4+3][ar+64]=v1.w;
            int c0 = bq*4;
            Bs2[br][2*c0+0]=pb.x; Bs2[br][2*c0+1]=pb.x;
            Bs2[br][2*c0+2]=pb.y; Bs2[br][2*c0+3]=pb.y;
            Bs2[br][2*c0+4]=pb.z; Bs2[br][2*c0+5]=pb.z;
            Bs2[br][2*c0+6]=pb.w; Bs2[br][2*c0+7]=pb.w;
        }
        __syncthreads();
        // prefetch next tile
        if (it+1 < nit){
            pa0 = *(const float4*)(A0p + (it+1)*16);
            pa1 = *(const float4*)(A1p + (it+1)*16);
            if (A2){ pg0 = *(const float4*)(G0p + (it+1)*16); pg1 = *(const float4*)(G1p + (it+1)*16); }
            pb  = *(const float4*)(Bp + (size_t)(it+1)*16*N);
        }
        // compute
        #pragma unroll
        for (int k=0;k<16;k++){
            ulonglong2 aA = *(const ulonglong2*)&As[k][tr*8];
            ulonglong2 aB = *(const ulonglong2*)&As[k][tr*8+4];
            ulonglong2 b1 = *(const ulonglong2*)&Bs2[k][tc*8];
            ulonglong2 b2 = *(const ulonglong2*)&Bs2[k][tc*8+4];
            ull a64[4] = {aA.x, aA.y, aB.x, aB.y};
            ull b64[4] = {b1.x, b1.y, b2.x, b2.y};
            #pragma unroll
            for (int i=0;i<4;i++){
                #pragma unroll
                for (int j=0;j<4;j++){
                    asm("fma.rn.f32x2 %0, %1, %2, %0;"
                        : "+l"(acc[i][j]) : "l"(a64[i]), "l"(b64[j]));
                }
            }
        }
        __syncthreads();
        if (++it == nit) break;
    }

    // epilogue
    #pragma unroll
    for (int i=0;i<4;i++){
        #pragma unroll
        for (int j=0;j<4;j++){
            float lo, hi;
            asm("mov.b64 {%0,%1}, %2;" : "=f"(lo), "=f"(hi) : "l"(acc[i][j]));
            int n = n0 + tc*4 + j;
            size_t m = (size_t)m0 + tr*8 + 2*i;
            float bv = bias ? bias[n] : 0.f;
            float v0 = lo + bv, v1 = hi + bv;
            if (n >= sigStart){ v0 = sigm(v0); v1 = sigm(v1); }
            size_t off0 = m*(size_t)N + n;
            size_t off1 = off0 + N;
            if (mulp){ v0 *= mulp[off0]; v1 *= mulp[off1]; }
            if (addp){ v0 += addp[off0]; v1 += addp[off1]; }
            C[off0] = v0; C[off1] = v1;
        }
    }
}

// ---------------- K6: windowed attention, one CTA per (b, w, h) ----------------
__global__ void attn_kernel(int blk){
    __shared__ float qs[NQ*DD];       // 32x32
    __shared__ float kv[NK*33];       // 128x32 padded (K tile, later reused as V tile)
    __shared__ float lb[NQ*129];      // bias -> logits -> attn, padded rows
    int w = blockIdx.x, h = blockIdx.y, b = blockIdx.z;
    int tid = threadIdx.x;            // 256
    size_t tokbase = (size_t)b*NN + (size_t)w*NQ;
    int kstart = w*NQ - 48;           // (NK-NQ)/2 = 48
    // load Q
    for (int i=tid; i<NQ*DD; i+=256){
        int r=i>>5, c=i&31;
        qs[i] = g_qh[(tokbase+r)*CA + h*DD + c];
    }
    // load K (clamped; masked later)
    for (int i=tid; i<NK*DD; i+=256){
        int r=i>>5, c=i&31;
        int src = kstart + r; src = min(max(src,0), NN-1);
        kv[r*33+c] = g_kh[((size_t)b*NN + src)*CA + h*DD + c];
    }
    // load bias plane (coalesced: stored [blk][h][row])
    const float* plane = g_biasbuf + ((size_t)blk*HH + h)*(size_t)ROWS;
    size_t rb = (((size_t)b*WW + w)*NQ)*NK;
    for (int i=tid; i<NQ*NK; i+=256){
        int q=i>>7, k=i&127;
        lb[q*129+k] = plane[rb + i];
    }
    __syncthreads();
    // logits: 4q x 4k tile per thread (k strided by 32 for conflict-free smem)
    {
        int qt = tid>>5, kt = tid&31;
        float acc[4][4] = {};
        #pragma unroll
        for (int d=0; d<DD; d++){
            float qa[4], kb[4];
            #pragma unroll
            for (int j=0;j<4;j++) qa[j] = qs[(qt*4+j)*DD + d];
            #pragma unroll
            for (int l=0;l<4;l++) kb[l] = kv[(kt+32*l)*33 + d];
            #pragma unroll
            for (int j=0;j<4;j++)
                #pragma unroll
                for (int l=0;l<4;l++) acc[j][l] += qa[j]*kb[l];
        }
        const float isd = 0.17677669529663687f;  // 1/sqrt(32)
        #pragma unroll
        for (int j=0;j<4;j++){
            #pragma unroll
            for (int l=0;l<4;l++){
                int q = qt*4+j, k = kt+32*l;
                int src = kstart + k;
                float v = (src>=0 && src<NN) ? acc[j][l]*isd + lb[q*129+k] : -1e9f;
                lb[q*129+k] = v;
            }
        }
    }
    __syncthreads();
    // load V into kv (K tile no longer needed)
    for (int i=tid; i<NK*DD; i+=256){
        int r=i>>5, c=i&31;
        int src = kstart + r; src = min(max(src,0), NN-1);
        kv[r*33+c] = g_vh[((size_t)b*NN + src)*CA + h*DD + c];
    }
    // softmax: 8 warps x 4 rows (lb only; overlaps with V load)
    {
        int wid = tid>>5, lane = tid&31;
        for (int rq=0; rq<4; rq++){
            int q = wid*4 + rq;
            float m = -1e30f;
            #pragma unroll
            for (int k=lane; k<NK; k+=32) m = fmaxf(m, lb[q*129+k]);
            #pragma unroll
            for (int o=16;o;o>>=1) m = fmaxf(m, __shfl_xor_sync(0xffffffffu, m, o));
            float ssum = 0.f;
            #pragma unroll
            for (int k=lane; k<NK; k+=32){
                float e = __expf(lb[q*129+k] - m);
                lb[q*129+k] = e; ssum += e;
            }
            #pragma unroll
            for (int o=16;o;o>>=1) ssum += __shfl_xor_sync(0xffffffffu, ssum, o);
            float invs = 1.f/ssum;
            #pragma unroll
            for (int k=lane; k<NK; k+=32) lb[q*129+k] *= invs;
        }
    }
    __syncthreads();
    // AV: 2q x 2d per thread, then gate-multiply and store
    {
        int qp = tid>>4, dp = tid&15;
        float av[2][2] = {};
        #pragma unroll 4
        for (int k=0;k<NK;k++){
            float p0 = lb[(qp*2  )*129 + k];
            float p1 = lb[(qp*2+1)*129 + k];
            float v0 = kv[k*33 + dp];
            float v1 = kv[k*33 + dp + 16];
            av[0][0]+=p0*v0; av[0][1]+=p0*v1; av[1][0]+=p1*v0; av[1][1]+=p1*v1;
        }
        #pragma unroll
        for (int a2=0;a2<2;a2++){
            #pragma unroll
            for (int b2=0;b2<2;b2++){
                int q = qp*2+a2, d = dp+16*b2;
                size_t off = (tokbase+q)*CA + h*DD + d;
                g_att[off] = g_gh[off]*av[a2][b2];
            }
        }
    }
}

// ---------------- host launcher ----------------
extern "C" void kernel_launch(void* const* d_in, const int* in_sizes, int n_in,
                              void* d_out, int out_size){
    const float* q_in   = (const float*)d_in[0];
    const float* s_in   = (const float*)d_in[1];
    const float* p_in   = (const float*)d_in[2];
    const float* adaln_scale_w = (const float*)d_in[3];
    const float* adaln_scale_b = (const float*)d_in[4];
    const float* adaln_shift_w = (const float*)d_in[5];
    const float* wq = (const float*)d_in[6];
    const float* bq = (const float*)d_in[7];
    const float* wk = (const float*)d_in[8];
    const float* wv = (const float*)d_in[9];
    const float* lnz_w = (const float*)d_in[10];
    const float* lnz_b = (const float*)d_in[11];
    const float* wb_pair = (const float*)d_in[12];
    const float* wg = (const float*)d_in[13];
    const float* wo = (const float*)d_in[14];
    const float* sgate_w = (const float*)d_in[15];
    const float* sgate_b = (const float*)d_in[16];
    const float* t_scale_w = (const float*)d_in[17];
    const float* t_scale_b = (const float*)d_in[18];
    const float* t_shift_w = (const float*)d_in[19];
    const float* t_wa = (const float*)d_in[20];
    const float* t_wb = (const float*)d_in[21];
    const float* t_wo = (const float*)d_in[22];
    const float* t_sgate_w = (const float*)d_in[23];
    const float* t_sgate_b = (const float*)d_in[24];
    float* out = (float*)d_out;

    float *p_sln, *p_gates, *p_aln, *p_tln, *p_q, *p_k, *p_v, *p_g, *p_att, *p_ao, *p_a, *hbuf;
    cudaGetSymbolAddress((void**)&p_sln,  g_sln);
    cudaGetSymbolAddress((void**)&p_gates,g_gates);
    cudaGetSymbolAddress((void**)&p_aln,  g_aln);
    cudaGetSymbolAddress((void**)&p_tln,  g_tln);
    cudaGetSymbolAddress((void**)&p_q,    g_qh);
    cudaGetSymbolAddress((void**)&p_k,    g_kh);
    cudaGetSymbolAddress((void**)&p_v,    g_vh);
    cudaGetSymbolAddress((void**)&p_g,    g_gh);
    cudaGetSymbolAddress((void**)&p_att,  g_att);
    cudaGetSymbolAddress((void**)&p_ao,   g_ao);
    cudaGetSymbolAddress((void**)&p_a,    g_a);
    cudaGetSymbolAddress((void**)&hbuf,   g_hid);
    float* p_ha = hbuf;
    float* p_hb = hbuf + (size_t)TT*HID;

    const int NOSIG = 1<<30;
    #define GATE(i,g) (p_gates + ((size_t)((i)*6+(g)))*((size_t)TT*CA))
    #define GEMM(A,A2,Bm,bias,mul,add,C,M,N,K,sig) \
        gemm_kernel<<<dim3((M)/128,(N)/64),256>>>((A),(A2),(Bm),(bias),(mul),(add),(C),(M),(N),(K),(sig))

    // stage 0: invariants
    sln_kernel<<<TT,128>>>(s_in);
    bias_kernel<<<ROWS/256,256>>>(p_in, lnz_w, lnz_b, wb_pair);
    for (int i=0;i<NB;i++){
        GEMM(p_sln,(const float*)0, adaln_scale_w+(size_t)i*CS*CA, adaln_scale_b+i*CA, (const float*)0,(const float*)0, GATE(i,0), TT,CA,CS, 0);
        GEMM(p_sln,(const float*)0, adaln_shift_w+(size_t)i*CS*CA, (const float*)0,    (const float*)0,(const float*)0, GATE(i,1), TT,CA,CS, NOSIG);
        GEMM(p_sln,(const float*)0, sgate_w      +(size_t)i*CS*CA, sgate_b+i*CA,       (const float*)0,(const float*)0, GATE(i,2), TT,CA,CS, 0);
        GEMM(p_sln,(const float*)0, t_scale_w    +(size_t)i*CS*CA, t_scale_b+i*CA,     (const float*)0,(const float*)0, GATE(i,3), TT,CA,CS, 0);
        GEMM(p_sln,(const float*)0, t_shift_w    +(size_t)i*CS*CA, (const float*)0,    (const float*)0,(const float*)0, GATE(i,4), TT,CA,CS, NOSIG);
        GEMM(p_sln,(const float*)0, t_sgate_w    +(size_t)i*CS*CA, t_sgate_b+i*CA,     (const float*)0,(const float*)0, GATE(i,5), TT,CA,CS, 0);
    }

    // stage 1: the 3 transformer blocks
    const float* acur = q_in;
    for (int i=0;i<NB;i++){
        lnmod_kernel<<<TT,128>>>(acur, i);
        GEMM(p_aln,(const float*)0, wq+(size_t)i*CA*CA, bq+i*CA,        (const float*)0,(const float*)0, p_q, TT,CA,CA, NOSIG);
        GEMM(p_aln,(const float*)0, wk+(size_t)i*CA*CA, (const float*)0,(const float*)0,(const float*)0, p_k, TT,CA,CA, NOSIG);
        GEMM(p_aln,(const float*)0, wv+(size_t)i*CA*CA, (const float*)0,(const float*)0,(const float*)0, p_v, TT,CA,CA, NOSIG);
        GEMM(p_aln,(const float*)0, wg+(size_t)i*CA*CA, (const float*)0,(const float*)0,(const float*)0, p_g, TT,CA,CA, 0);
        attn_kernel<<<dim3(WW,HH,Bb),256>>>(i);
        GEMM(p_att,(const float*)0, wo+(size_t)i*CA*CA, (const float*)0, GATE(i,2), (const float*)0, p_ao, TT,CA,CA, NOSIG);
        GEMM(p_tln,(const float*)0, t_wa+(size_t)i*CA*HID, (const float*)0,(const float*)0,(const float*)0, p_ha, TT,HID,CA, NOSIG);
        GEMM(p_tln,(const float*)0, t_wb+(size_t)i*CA*HID, (const float*)0,(const float*)0,(const float*)0, p_hb, TT,HID,CA, NOSIG);
        float* dst = (i==NB-1) ? out : p_a;
        GEMM(p_ha, p_hb, t_wo+(size_t)i*HID*CA, (const float*)0, GATE(i,5), p_ao, dst, TT,CA,HID, NOSIG);
        acur = p_a;
    }
    #undef GEMM
    #undef GATE
    (void)in_sizes; (void)n_in; (void)out_size;
}

// round 4
// speedup vs baseline: 1.5091x; 1.5091x over previous
#include <cuda_runtime.h>
#include <cuda_bf16.h>
#include <math.h>

#define Bb  2
#define NN  8192
#define CA  128
#define CS  384
#define CZ  16
#define HH  4
#define DD  32
#define NQ  32
#define NK  128
#define NB  3
#define WW  256
#define HID 256
#define TT  (Bb*NN)          /* 16384 tokens */
#define ROWS 2097152         /* B*W*NQ*NK */

// ---------------- scratch (device globals; no allocation allowed) ----------------
__device__ float g_sln [(size_t)TT*CS];
__device__ float g_gates[NB*6][(size_t)TT*CA];
__device__ float g_biasbuf[(size_t)NB*HH*ROWS];  // [blk][h][row]
__device__ float g_aln[(size_t)TT*CA];
__device__ float g_tln[(size_t)TT*CA];
__device__ float g_qh [(size_t)TT*CA];
__device__ float g_kh [(size_t)TT*CA];
__device__ float g_vh [(size_t)TT*CA];
__device__ float g_gh [(size_t)TT*CA];
__device__ float g_att[(size_t)TT*CA];
__device__ float g_ao [(size_t)TT*CA];
__device__ float g_a  [(size_t)TT*CA];
__device__ float g_hid[(size_t)2*TT*HID];        // ha | hb

__device__ __forceinline__ float sigm(float x){ return 1.f/(1.f+__expf(-x)); }

__device__ __forceinline__ float2 split_tf32(float x){
    float hi, lo;
    asm("cvt.rna.tf32.f32 %0, %1;" : "=f"(hi) : "f"(x));
    float r = x - hi;
    asm("cvt.rna.tf32.f32 %0, %1;" : "=f"(lo) : "f"(r));
    return make_float2(hi, lo);
}

__device__ __forceinline__ void mma_tf32(float* c, const unsigned* a, const unsigned* b){
    asm volatile(
        "mma.sync.aligned.m16n8k8.row.col.f32.tf32.tf32.f32 "
        "{%0,%1,%2,%3},{%4,%5,%6,%7},{%8,%9},{%0,%1,%2,%3};"
        : "+f"(c[0]), "+f"(c[1]), "+f"(c[2]), "+f"(c[3])
        : "r"(a[0]), "r"(a[1]), "r"(a[2]), "r"(a[3]), "r"(b[0]), "r"(b[1]));
}

// reduce (sum, sumsq) across a 128-thread block
__device__ __forceinline__ void blockReduce2_128(float& s, float& q){
    __shared__ float sb[8];
    #pragma unroll
    for (int o=16;o;o>>=1){
        s += __shfl_xor_sync(0xffffffffu, s, o);
        q += __shfl_xor_sync(0xffffffffu, q, o);
    }
    int wid = threadIdx.x>>5;
    if ((threadIdx.x&31)==0){ sb[wid*2]=s; sb[wid*2+1]=q; }
    __syncthreads();
    s = sb[0]+sb[2]+sb[4]+sb[6];
    q = sb[1]+sb[3]+sb[5]+sb[7];
}

// ---------------- K1: layernorm of s (once) ----------------
__global__ void sln_kernel(const float* __restrict__ s){
    int t = blockIdx.x, tid = threadIdx.x;
    const float* row = s + (size_t)t*CS;
    float v0=row[tid], v1=row[tid+128], v2=row[tid+256];
    float su=v0+v1+v2, sq=v0*v0+v1*v1+v2*v2;
    blockReduce2_128(su,sq);
    float mean = su*(1.f/CS);
    float var  = sq*(1.f/CS) - mean*mean;
    float inv  = rsqrtf(var + 1e-5f);
    float* o = g_sln + (size_t)t*CS;
    o[tid]=(v0-mean)*inv; o[tid+128]=(v1-mean)*inv; o[tid+256]=(v2-mean)*inv;
}

// ---------------- K3: pair bias for all 3 blocks (once) ----------------
__global__ void bias_kernel(const float* __restrict__ p, const float* __restrict__ lnz_w,
                            const float* __restrict__ lnz_b, const float* __restrict__ wb){
    __shared__ float s_w[NB*CZ], s_b[NB*CZ], s_wb[NB*CZ*HH];
    int tid = threadIdx.x;
    if (tid < NB*CZ){ s_w[tid]=lnz_w[tid]; s_b[tid]=lnz_b[tid]; }
    if (tid < NB*CZ*HH) s_wb[tid]=wb[tid];
    __syncthreads();
    size_t r = (size_t)blockIdx.x*blockDim.x + tid;
    if (r >= (size_t)ROWS) return;
    const float4* p4 = (const float4*)(p + r*CZ);
    float z[16];
    float4 q0=p4[0], q1=p4[1], q2=p4[2], q3=p4[3];
    z[0]=q0.x; z[1]=q0.y; z[2]=q0.z; z[3]=q0.w;
    z[4]=q1.x; z[5]=q1.y; z[6]=q1.z; z[7]=q1.w;
    z[8]=q2.x; z[9]=q2.y; z[10]=q2.z; z[11]=q2.w;
    z[12]=q3.x; z[13]=q3.y; z[14]=q3.z; z[15]=q3.w;
    float su=0, sq=0;
    #pragma unroll
    for (int c=0;c<16;c++){ su+=z[c]; sq+=z[c]*z[c]; }
    float mean=su*(1.f/16.f), var=sq*(1.f/16.f)-mean*mean;
    float inv=rsqrtf(var+1e-5f);
    #pragma unroll
    for (int c=0;c<16;c++) z[c]=(z[c]-mean)*inv;
    #pragma unroll
    for (int i=0;i<NB;i++){
        float o0=0,o1=0,o2=0,o3=0;
        #pragma unroll
        for (int c=0;c<16;c++){
            float zz = z[c]*s_w[i*16+c] + s_b[i*16+c];
            const float* w4 = &s_wb[(i*16+c)*4];
            o0 += zz*w4[0]; o1 += zz*w4[1]; o2 += zz*w4[2]; o3 += zz*w4[3];
        }
        size_t base = ((size_t)i*HH)*ROWS + r;
        g_biasbuf[base]        = o0;
        g_biasbuf[base+ROWS]   = o1;
        g_biasbuf[base+2*(size_t)ROWS] = o2;
        g_biasbuf[base+3*(size_t)ROWS] = o3;
    }
}

// ---------------- K4: LN(a) + both modulations (per block) ----------------
__global__ void lnmod_kernel(const float* __restrict__ a, int blk){
    int t = blockIdx.x, c = threadIdx.x;
    float x = a[(size_t)t*CA + c];
    float su=x, sq=x*x;
    blockReduce2_128(su,sq);
    float mean=su*(1.f/CA), var=sq*(1.f/CA)-mean*mean;
    float xn=(x-mean)*rsqrtf(var+1e-5f);
    size_t o=(size_t)t*CA+c;
    g_aln[o] = g_gates[blk*6+0][o]*xn + g_gates[blk*6+1][o];
    g_tln[o] = g_gates[blk*6+3][o]*xn + g_gates[blk*6+4][o];
}

// ---------------- GEMM: tensor-core tf32 (3xTF32 for fp32 precision) ----------------
// C[M,N] = A[M,K] @ B[K,N] + epilogue. CTA tile 64(M) x 128(N), BK=16, 256 thr.
// 8 warps in 2(m) x 4(n), each warp 32x32 via m16n8k8 tf32 mma.
// hi/lo tf32 parts interleaved in smem: every fragment element is one LDS.64.
// A2 != null: A_eff = silu(A)*A2. epilogue: +bias[n]; sigmoid n>=sigStart; *mulp; +addp.
#define A_STRIDE 40   /* 2*16 + 8 pad */
#define B_STRIDE 264  /* 2*128 + 8 pad */
__global__ __launch_bounds__(256) void gemm_kernel(
        const float* __restrict__ A, const float* __restrict__ A2,
        const float* __restrict__ Bm, const float* __restrict__ bias,
        const float* __restrict__ mulp, const float* __restrict__ addp,
        float* __restrict__ C, int M, int N, int K, int sigStart){
    __shared__ float Ahl[64*A_STRIDE];
    __shared__ float Bhl[16*B_STRIDE];
    int m0 = blockIdx.x*64, n0 = blockIdx.y*128;
    int tid = threadIdx.x, lane = tid&31, wid = tid>>5;
    int g = lane>>2, tig = lane&3;
    int wm = (wid&1)*32, wn = (wid>>1)*32;
    float acc[2][4][4] = {};
    const int nstage = K>>4;

    int ar = tid>>2, akq = tid&3;     // A: row 0..63, k-float4 0..3
    int br = tid>>5, bnq = tid&31;    // B: k rows br, br+8; n-float4 0..31
    const float* Ap  = A + (size_t)(m0+ar)*K + akq*4;
    const float* Gp  = A2 ? A2 + (size_t)(m0+ar)*K + akq*4 : (const float*)0;
    const float* Bp0 = Bm + (size_t)br*N + n0 + bnq*4;
    const float* Bp1 = Bm + (size_t)(br+8)*N + n0 + bnq*4;

    float4 pa, pg, pb0, pb1;
    pg = make_float4(0.f,0.f,0.f,0.f);
    pa  = *(const float4*)Ap;
    if (A2) pg = *(const float4*)Gp;
    pb0 = *(const float4*)Bp0;
    pb1 = *(const float4*)Bp1;

    for (int it=0;;){
        // split to hi/lo and store interleaved
        {
            float4 v = pa;
            if (A2){
                v.x = v.x*sigm(v.x)*pg.x; v.y = v.y*sigm(v.y)*pg.y;
                v.z = v.z*sigm(v.z)*pg.z; v.w = v.w*sigm(v.w)*pg.w;
            }
            float2 sx=split_tf32(v.x), sy=split_tf32(v.y), sz=split_tf32(v.z), sw=split_tf32(v.w);
            float* da = &Ahl[ar*A_STRIDE + akq*8];
            ((float4*)da)[0] = make_float4(sx.x,sx.y,sy.x,sy.y);
            ((float4*)da)[1] = make_float4(sz.x,sz.y,sw.x,sw.y);

            float2 bx=split_tf32(pb0.x), by=split_tf32(pb0.y), bz=split_tf32(pb0.z), bw=split_tf32(pb0.w);
            float* db0 = &Bhl[br*B_STRIDE + bnq*8];
            ((float4*)db0)[0] = make_float4(bx.x,bx.y,by.x,by.y);
            ((float4*)db0)[1] = make_float4(bz.x,bz.y,bw.x,bw.y);
            bx=split_tf32(pb1.x); by=split_tf32(pb1.y); bz=split_tf32(pb1.z); bw=split_tf32(pb1.w);
            float* db1 = &Bhl[(br+8)*B_STRIDE + bnq*8];
            ((float4*)db1)[0] = make_float4(bx.x,bx.y,by.x,by.y);
            ((float4*)db1)[1] = make_float4(bz.x,bz.y,bw.x,bw.y);
        }
        __syncthreads();
        // prefetch next tile
        if (it+1 < nstage){
            pa  = *(const float4*)(Ap + (it+1)*16);
            if (A2) pg = *(const float4*)(Gp + (it+1)*16);
            pb0 = *(const float4*)(Bp0 + (size_t)(it+1)*16*N);
            pb1 = *(const float4*)(Bp1 + (size_t)(it+1)*16*N);
        }
        // compute: two k8 steps
        #pragma unroll
        for (int ks=0; ks<16; ks+=8){
            unsigned ah[2][4], al[2][4], bh[4][2], bl[4][2];
            #pragma unroll
            for (int mt=0; mt<2; mt++){
                int row = wm + mt*16 + g;
                float2 p0 = *(const float2*)&Ahl[ row   *A_STRIDE + 2*(ks+tig)  ];
                float2 p1 = *(const float2*)&Ahl[(row+8)*A_STRIDE + 2*(ks+tig)  ];
                float2 p2 = *(const float2*)&Ahl[ row   *A_STRIDE + 2*(ks+tig+4)];
                float2 p3 = *(const float2*)&Ahl[(row+8)*A_STRIDE + 2*(ks+tig+4)];
                ah[mt][0]=__float_as_uint(p0.x); al[mt][0]=__float_as_uint(p0.y);
                ah[mt][1]=__float_as_uint(p1.x); al[mt][1]=__float_as_uint(p1.y);
                ah[mt][2]=__float_as_uint(p2.x); al[mt][2]=__float_as_uint(p2.y);
                ah[mt][3]=__float_as_uint(p3.x); al[mt][3]=__float_as_uint(p3.y);
            }
            #pragma unroll
            for (int nt=0; nt<4; nt++){
                int n = wn + nt*8 + g;
                float2 q0 = *(const float2*)&Bhl[(ks+tig  )*B_STRIDE + 2*n];
                float2 q1 = *(const float2*)&Bhl[(ks+tig+4)*B_STRIDE + 2*n];
                bh[nt][0]=__float_as_uint(q0.x); bl[nt][0]=__float_as_uint(q0.y);
                bh[nt][1]=__float_as_uint(q1.x); bl[nt][1]=__float_as_uint(q1.y);
            }
            #pragma unroll
            for (int mt=0; mt<2; mt++){
                #pragma unroll
                for (int nt=0; nt<4; nt++){
                    mma_tf32(acc[mt][nt], ah[mt], bh[nt]);
                    mma_tf32(acc[mt][nt], ah[mt], bl[nt]);
                    mma_tf32(acc[mt][nt], al[mt], bh[nt]);
                }
            }
        }
        __syncthreads();
        if (++it == nstage) break;
    }

    // epilogue
    #pragma unroll
    for (int mt=0; mt<2; mt++){
        #pragma unroll
        for (int nt=0; nt<4; nt++){
            int row0 = m0 + wm + mt*16 + g;
            int row1 = row0 + 8;
            int col  = n0 + wn + nt*8 + 2*tig;
            float b0 = bias ? bias[col]   : 0.f;
            float b1 = bias ? bias[col+1] : 0.f;
            float e0 = acc[mt][nt][0] + b0, e1 = acc[mt][nt][1] + b1;
            float e2 = acc[mt][nt][2] + b0, e3 = acc[mt][nt][3] + b1;
            if (col >= sigStart){ e0=sigm(e0); e1=sigm(e1); e2=sigm(e2); e3=sigm(e3); }
            size_t o0 = (size_t)row0*N + col;
            size_t o1 = (size_t)row1*N + col;
            if (mulp){ e0*=mulp[o0]; e1*=mulp[o0+1]; e2*=mulp[o1]; e3*=mulp[o1+1]; }
            if (addp){ e0+=addp[o0]; e1+=addp[o0+1]; e2+=addp[o1]; e3+=addp[o1+1]; }
            *(float2*)&C[o0] = make_float2(e0,e1);
            *(float2*)&C[o1] = make_float2(e2,e3);
        }
    }
}

// ---------------- K6: windowed attention, one CTA per (b, w, h) ----------------
__global__ void attn_kernel(int blk){
    __shared__ float qs[NQ*DD];       // 32x32
    __shared__ float kv[NK*33];       // 128x32 padded (K tile, later reused as V tile)
    __shared__ float lb[NQ*129];      // bias -> logits -> attn, padded rows
    int w = blockIdx.x, h = blockIdx.y, b = blockIdx.z;
    int tid = threadIdx.x;            // 256
    size_t tokbase = (size_t)b*NN + (size_t)w*NQ;
    int kstart = w*NQ - 48;           // (NK-NQ)/2 = 48
    for (int i=tid; i<NQ*DD; i+=256){
        int r=i>>5, c=i&31;
        qs[i] = g_qh[(tokbase+r)*CA + h*DD + c];
    }
    for (int i=tid; i<NK*DD; i+=256){
        int r=i>>5, c=i&31;
        int src = kstart + r; src = min(max(src,0), NN-1);
        kv[r*33+c] = g_kh[((size_t)b*NN + src)*CA + h*DD + c];
    }
    const float* plane = g_biasbuf + ((size_t)blk*HH + h)*(size_t)ROWS;
    size_t rb = (((size_t)b*WW + w)*NQ)*NK;
    for (int i=tid; i<NQ*NK; i+=256){
        int q=i>>7, k=i&127;
        lb[q*129+k] = plane[rb + i];
    }
    __syncthreads();
    {
        int qt = tid>>5, kt = tid&31;
        float acc[4][4] = {};
        #pragma unroll
        for (int d=0; d<DD; d++){
            float qa[4], kb[4];
            #pragma unroll
            for (int j=0;j<4;j++) qa[j] = qs[(qt*4+j)*DD + d];
            #pragma unroll
            for (int l=0;l<4;l++) kb[l] = kv[(kt+32*l)*33 + d];
            #pragma unroll
            for (int j=0;j<4;j++)
                #pragma unroll
                for (int l=0;l<4;l++) acc[j][l] += qa[j]*kb[l];
        }
        const float isd = 0.17677669529663687f;  // 1/sqrt(32)
        #pragma unroll
        for (int j=0;j<4;j++){
            #pragma unroll
            for (int l=0;l<4;l++){
                int q = qt*4+j, k = kt+32*l;
                int src = kstart + k;
                float v = (src>=0 && src<NN) ? acc[j][l]*isd + lb[q*129+k] : -1e9f;
                lb[q*129+k] = v;
            }
        }
    }
    __syncthreads();
    for (int i=tid; i<NK*DD; i+=256){
        int r=i>>5, c=i&31;
        int src = kstart + r; src = min(max(src,0), NN-1);
        kv[r*33+c] = g_vh[((size_t)b*NN + src)*CA + h*DD + c];
    }
    {
        int wid = tid>>5, lane = tid&31;
        for (int rq=0; rq<4; rq++){
            int q = wid*4 + rq;
            float m = -1e30f;
            #pragma unroll
            for (int k=lane; k<NK; k+=32) m = fmaxf(m, lb[q*129+k]);
            #pragma unroll
            for (int o=16;o;o>>=1) m = fmaxf(m, __shfl_xor_sync(0xffffffffu, m, o));
            float ssum = 0.f;
            #pragma unroll
            for (int k=lane; k<NK; k+=32){
                float e = __expf(lb[q*129+k] - m);
                lb[q*129+k] = e; ssum += e;
            }
            #pragma unroll
            for (int o=16;o;o>>=1) ssum += __shfl_xor_sync(0xffffffffu, ssum, o);
            float invs = 1.f/ssum;
            #pragma unroll
            for (int k=lane; k<NK; k+=32) lb[q*129+k] *= invs;
        }
    }
    __syncthreads();
    {
        int qp = tid>>4, dp = tid&15;
        float av[2][2] = {};
        #pragma unroll 4
        for (int k=0;k<NK;k++){
            float p0 = lb[(qp*2  )*129 + k];
            float p1 = lb[(qp*2+1)*129 + k];
            float v0 = kv[k*33 + dp];
            float v1 = kv[k*33 + dp + 16];
            av[0][0]+=p0*v0; av[0][1]+=p0*v1; av[1][0]+=p1*v0; av[1][1]+=p1*v1;
        }
        #pragma unroll
        for (int a2=0;a2<2;a2++){
            #pragma unroll
            for (int b2=0;b2<2;b2++){
                int q = qp*2+a2, d = dp+16*b2;
                size_t off = (tokbase+q)*CA + h*DD + d;
                g_att[off] = g_gh[off]*av[a2][b2];
            }
        }
    }
}

// ---------------- host launcher ----------------
extern "C" void kernel_launch(void* const* d_in, const int* in_sizes, int n_in,
                              void* d_out, int out_size){
    const float* q_in   = (const float*)d_in[0];
    const float* s_in   = (const float*)d_in[1];
    const float* p_in   = (const float*)d_in[2];
    const float* adaln_scale_w = (const float*)d_in[3];
    const float* adaln_scale_b = (const float*)d_in[4];
    const float* adaln_shift_w = (const float*)d_in[5];
    const float* wq = (const float*)d_in[6];
    const float* bq = (const float*)d_in[7];
    const float* wk = (const float*)d_in[8];
    const float* wv = (const float*)d_in[9];
    const float* lnz_w = (const float*)d_in[10];
    const float* lnz_b = (const float*)d_in[11];
    const float* wb_pair = (const float*)d_in[12];
    const float* wg = (const float*)d_in[13];
    const float* wo = (const float*)d_in[14];
    const float* sgate_w = (const float*)d_in[15];
    const float* sgate_b = (const float*)d_in[16];
    const float* t_scale_w = (const float*)d_in[17];
    const float* t_scale_b = (const float*)d_in[18];
    const float* t_shift_w = (const float*)d_in[19];
    const float* t_wa = (const float*)d_in[20];
    const float* t_wb = (const float*)d_in[21];
    const float* t_wo = (const float*)d_in[22];
    const float* t_sgate_w = (const float*)d_in[23];
    const float* t_sgate_b = (const float*)d_in[24];
    float* out = (float*)d_out;

    float *p_sln, *p_gates, *p_aln, *p_tln, *p_q, *p_k, *p_v, *p_g, *p_att, *p_ao, *p_a, *hbuf;
    cudaGetSymbolAddress((void**)&p_sln,  g_sln);
    cudaGetSymbolAddress((void**)&p_gates,g_gates);
    cudaGetSymbolAddress((void**)&p_aln,  g_aln);
    cudaGetSymbolAddress((void**)&p_tln,  g_tln);
    cudaGetSymbolAddress((void**)&p_q,    g_qh);
    cudaGetSymbolAddress((void**)&p_k,    g_kh);
    cudaGetSymbolAddress((void**)&p_v,    g_vh);
    cudaGetSymbolAddress((void**)&p_g,    g_gh);
    cudaGetSymbolAddress((void**)&p_att,  g_att);
    cudaGetSymbolAddress((void**)&p_ao,   g_ao);
    cudaGetSymbolAddress((void**)&p_a,    g_a);
    cudaGetSymbolAddress((void**)&hbuf,   g_hid);
    float* p_ha = hbuf;
    float* p_hb = hbuf + (size_t)TT*HID;

    const int NOSIG = 1<<30;
    #define GATE(i,g) (p_gates + ((size_t)((i)*6+(g)))*((size_t)TT*CA))
    #define GEMM(A,A2,Bm,bias,mul,add,C,M,N,K,sig) \
        gemm_kernel<<<dim3((M)/64,(N)/128),256>>>((A),(A2),(Bm),(bias),(mul),(add),(C),(M),(N),(K),(sig))

    // stage 0: invariants
    sln_kernel<<<TT,128>>>(s_in);
    bias_kernel<<<ROWS/256,256>>>(p_in, lnz_w, lnz_b, wb_pair);
    for (int i=0;i<NB;i++){
        GEMM(p_sln,(const float*)0, adaln_scale_w+(size_t)i*CS*CA, adaln_scale_b+i*CA, (const float*)0,(const float*)0, GATE(i,0), TT,CA,CS, 0);
        GEMM(p_sln,(const float*)0, adaln_shift_w+(size_t)i*CS*CA, (const float*)0,    (const float*)0,(const float*)0, GATE(i,1), TT,CA,CS, NOSIG);
        GEMM(p_sln,(const float*)0, sgate_w      +(size_t)i*CS*CA, sgate_b+i*CA,       (const float*)0,(const float*)0, GATE(i,2), TT,CA,CS, 0);
        GEMM(p_sln,(const float*)0, t_scale_w    +(size_t)i*CS*CA, t_scale_b+i*CA,     (const float*)0,(const float*)0, GATE(i,3), TT,CA,CS, 0);
        GEMM(p_sln,(const float*)0, t_shift_w    +(size_t)i*CS*CA, (const float*)0,    (const float*)0,(const float*)0, GATE(i,4), TT,CA,CS, NOSIG);
        GEMM(p_sln,(const float*)0, t_sgate_w    +(size_t)i*CS*CA, t_sgate_b+i*CA,     (const float*)0,(const float*)0, GATE(i,5), TT,CA,CS, 0);
    }

    // stage 1: the 3 transformer blocks
    const float* acur = q_in;
    for (int i=0;i<NB;i++){
        lnmod_kernel<<<TT,128>>>(acur, i);
        GEMM(p_aln,(const float*)0, wq+(size_t)i*CA*CA, bq+i*CA,        (const float*)0,(const float*)0, p_q, TT,CA,CA, NOSIG);
        GEMM(p_aln,(const float*)0, wk+(size_t)i*CA*CA, (const float*)0,(const float*)0,(const float*)0, p_k, TT,CA,CA, NOSIG);
        GEMM(p_aln,(const float*)0, wv+(size_t)i*CA*CA, (const float*)0,(const float*)0,(const float*)0, p_v, TT,CA,CA, NOSIG);
        GEMM(p_aln,(const float*)0, wg+(size_t)i*CA*CA, (const float*)0,(const float*)0,(const float*)0, p_g, TT,CA,CA, 0);
        attn_kernel<<<dim3(WW,HH,Bb),256>>>(i);
        GEMM(p_att,(const float*)0, wo+(size_t)i*CA*CA, (const float*)0, GATE(i,2), (const float*)0, p_ao, TT,CA,CA, NOSIG);
        GEMM(p_tln,(const float*)0, t_wa+(size_t)i*CA*HID, (const float*)0,(const float*)0,(const float*)0, p_ha, TT,HID,CA, NOSIG);
        GEMM(p_tln,(const float*)0, t_wb+(size_t)i*CA*HID, (const float*)0,(const float*)0,(const float*)0, p_hb, TT,HID,CA, NOSIG);
        float* dst = (i==NB-1) ? out : p_a;
        GEMM(p_ha, p_hb, t_wo+(size_t)i*HID*CA, (const float*)0, GATE(i,5), p_ao, dst, TT,CA,HID, NOSIG);
        acur = p_a;
    }
    #undef GEMM
    #undef GATE
    (void)in_sizes; (void)n_in; (void)out_size;
}

// round 6
// speedup vs baseline: 1.7893x; 1.1857x over previous
#include <cuda_runtime.h>
#include <cuda_bf16.h>
#include <math.h>

#define Bb  2
#define NN  8192
#define CA  128
#define CS  384
#define CZ  16
#define HH  4
#define DD  32
#define NQ  32
#define NK  128
#define NB  3
#define WW  256
#define HID 256
#define TT  (Bb*NN)          /* 16384 tokens */
#define ROWS 2097152         /* B*W*NQ*NK */
#define NG  2304             /* 18*128 packed gate width */

// ---------------- scratch (device globals; no allocation allowed) ----------------
__device__ float g_sln   [(size_t)TT*CS];
__device__ float g_gatesP[(size_t)TT*NG];        // packed gates [t][(blk*6+g)*128+c]
__device__ float g_biasbuf[(size_t)NB*HH*ROWS];  // [blk][h][row]
__device__ float g_aln[(size_t)TT*CA];
__device__ float g_tln[(size_t)TT*CA];
__device__ float g_qkvg[(size_t)TT*512];         // q|k|v|g packed
__device__ float g_att[(size_t)TT*CA];
__device__ float g_ao [(size_t)TT*CA];
__device__ float g_a  [(size_t)TT*CA];
__device__ float g_hid[(size_t)TT*512];          // ha|hb packed
// packed weights/biases (rebuilt every launch from inputs)
__device__ float g_wgate[(size_t)CS*NG];
__device__ float g_bgate[NG];
__device__ float g_wqkvg[(size_t)NB*CA*512];
__device__ float g_bqkvg[NB*512];
__device__ float g_whid [(size_t)NB*CA*512];

__device__ __forceinline__ float sigm(float x){ return 1.f/(1.f+__expf(-x)); }

__device__ __forceinline__ float2 split_tf32(float x){
    float hi, lo;
    asm("cvt.rna.tf32.f32 %0, %1;" : "=f"(hi) : "f"(x));
    float r = x - hi;
    asm("cvt.rna.tf32.f32 %0, %1;" : "=f"(lo) : "f"(r));
    return make_float2(hi, lo);
}

__device__ __forceinline__ void mma_tf32(float* c, const unsigned* a, const unsigned* b){
    asm volatile(
        "mma.sync.aligned.m16n8k8.row.col.f32.tf32.tf32.f32 "
        "{%0,%1,%2,%3},{%4,%5,%6,%7},{%8,%9},{%0,%1,%2,%3};"
        : "+f"(c[0]), "+f"(c[1]), "+f"(c[2]), "+f"(c[3])
        : "r"(a[0]), "r"(a[1]), "r"(a[2]), "r"(a[3]), "r"(b[0]), "r"(b[1]));
}

__device__ __forceinline__ void blockReduce2_128(float& s, float& q){
    __shared__ float sb[8];
    #pragma unroll
    for (int o=16;o;o>>=1){
        s += __shfl_xor_sync(0xffffffffu, s, o);
        q += __shfl_xor_sync(0xffffffffu, q, o);
    }
    int wid = threadIdx.x>>5;
    if ((threadIdx.x&31)==0){ sb[wid*2]=s; sb[wid*2+1]=q; }
    __syncthreads();
    s = sb[0]+sb[2]+sb[4]+sb[6];
    q = sb[1]+sb[3]+sb[5]+sb[7];
}

// ---------------- weight/bias packing (once per launch) ----------------
__global__ void pack_kernel(
    const float* __restrict__ aw,  const float* __restrict__ ashw,
    const float* __restrict__ sgw, const float* __restrict__ tsw,
    const float* __restrict__ tshw,const float* __restrict__ tsgw,
    const float* __restrict__ a_sb,const float* __restrict__ sg_b,
    const float* __restrict__ ts_b,const float* __restrict__ tsg_b,
    const float* __restrict__ wq,  const float* __restrict__ bq,
    const float* __restrict__ wk,  const float* __restrict__ wv,
    const float* __restrict__ wg,  const float* __restrict__ twa,
    const float* __restrict__ twb)
{
    int idx = blockIdx.x*256 + threadIdx.x;
    const int R1 = 18*CS*CA;      // 884736
    const int R2 = NB*CA*512;     // 196608
    const int R3 = NB*CA*512;
    if (idx < R1){
        int k = idx / NG, r = idx % NG;
        int gi = r >> 7, c = r & 127;
        int i = gi/6, g = gi - i*6;
        const float* src;
        switch(g){
            case 0: src = aw;  break;
            case 1: src = ashw;break;
            case 2: src = sgw; break;
            case 3: src = tsw; break;
            case 4: src = tshw;break;
            default:src = tsgw;break;
        }
        g_wgate[idx] = src[((size_t)i*CS + k)*CA + c];
        return;
    }
    idx -= R1;
    if (idx < R2){
        int r = idx % (CA*512);
        int blk = idx / (CA*512);
        int k = r >> 9, j = r & 511;
        float v;
        if (j < 128)      v = wq[((size_t)blk*CA + k)*128 + j];
        else if (j < 256) v = wk[((size_t)blk*CA + k)*128 + (j-128)];
        else if (j < 384) v = wv[((size_t)blk*CA + k)*128 + (j-256)];
        else              v = wg[((size_t)blk*CA + k)*128 + (j-384)];
        g_wqkvg[idx] = v;
        return;
    }
    idx -= R2;
    if (idx < R3){
        int r = idx % (CA*512);
        int blk = idx / (CA*512);
        int k = r >> 9, j = r & 511;
        g_whid[idx] = (j<256) ? twa[((size_t)blk*CA + k)*256 + j]
                              : twb[((size_t)blk*CA + k)*256 + (j-256)];
        return;
    }
    idx -= R3;
    if (idx < NG){
        int gi = idx >> 7, c = idx & 127;
        int i = gi/6, g = gi - i*6;
        float v = 0.f;
        if (g==0) v = a_sb[i*128+c];
        else if (g==2) v = sg_b[i*128+c];
        else if (g==3) v = ts_b[i*128+c];
        else if (g==5) v = tsg_b[i*128+c];
        g_bgate[idx] = v;
        return;
    }
    idx -= NG;
    if (idx < NB*512){
        int blk = idx >> 9, j = idx & 511;
        g_bqkvg[idx] = (j<128) ? bq[blk*128 + j] : 0.f;
    }
}

// ---------------- K1: layernorm of s (once) ----------------
__global__ void sln_kernel(const float* __restrict__ s){
    int t = blockIdx.x, tid = threadIdx.x;
    const float* row = s + (size_t)t*CS;
    float v0=row[tid], v1=row[tid+128], v2=row[tid+256];
    float su=v0+v1+v2, sq=v0*v0+v1*v1+v2*v2;
    blockReduce2_128(su,sq);
    float mean = su*(1.f/CS);
    float var  = sq*(1.f/CS) - mean*mean;
    float inv  = rsqrtf(var + 1e-5f);
    float* o = g_sln + (size_t)t*CS;
    o[tid]=(v0-mean)*inv; o[tid+128]=(v1-mean)*inv; o[tid+256]=(v2-mean)*inv;
}

// ---------------- K3: pair bias for all 3 blocks (once) ----------------
__global__ void bias_kernel(const float* __restrict__ p, const float* __restrict__ lnz_w,
                            const float* __restrict__ lnz_b, const float* __restrict__ wb){
    __shared__ float s_w[NB*CZ], s_b[NB*CZ], s_wb[NB*CZ*HH];
    int tid = threadIdx.x;
    if (tid < NB*CZ){ s_w[tid]=lnz_w[tid]; s_b[tid]=lnz_b[tid]; }
    if (tid < NB*CZ*HH) s_wb[tid]=wb[tid];
    __syncthreads();
    size_t r = (size_t)blockIdx.x*blockDim.x + tid;
    if (r >= (size_t)ROWS) return;
    const float4* p4 = (const float4*)(p + r*CZ);
    float z[16];
    float4 q0=p4[0], q1=p4[1], q2=p4[2], q3=p4[3];
    z[0]=q0.x; z[1]=q0.y; z[2]=q0.z; z[3]=q0.w;
    z[4]=q1.x; z[5]=q1.y; z[6]=q1.z; z[7]=q1.w;
    z[8]=q2.x; z[9]=q2.y; z[10]=q2.z; z[11]=q2.w;
    z[12]=q3.x; z[13]=q3.y; z[14]=q3.z; z[15]=q3.w;
    float su=0, sq=0;
    #pragma unroll
    for (int c=0;c<16;c++){ su+=z[c]; sq+=z[c]*z[c]; }
    float mean=su*(1.f/16.f), var=sq*(1.f/16.f)-mean*mean;
    float inv=rsqrtf(var+1e-5f);
    #pragma unroll
    for (int c=0;c<16;c++) z[c]=(z[c]-mean)*inv;
    #pragma unroll
    for (int i=0;i<NB;i++){
        float o0=0,o1=0,o2=0,o3=0;
        #pragma unroll
        for (int c=0;c<16;c++){
            float zz = z[c]*s_w[i*16+c] + s_b[i*16+c];
            const float* w4 = &s_wb[(i*16+c)*4];
            o0 += zz*w4[0]; o1 += zz*w4[1]; o2 += zz*w4[2]; o3 += zz*w4[3];
        }
        size_t base = ((size_t)i*HH)*ROWS + r;
        g_biasbuf[base]        = o0;
        g_biasbuf[base+ROWS]   = o1;
        g_biasbuf[base+2*(size_t)ROWS] = o2;
        g_biasbuf[base+3*(size_t)ROWS] = o3;
    }
}

// ---------------- K4: LN(a) + both modulations (per block) ----------------
__global__ void lnmod_kernel(const float* __restrict__ a, int blk){
    int t = blockIdx.x, c = threadIdx.x;
    float x = a[(size_t)t*CA + c];
    float su=x, sq=x*x;
    blockReduce2_128(su,sq);
    float mean=su*(1.f/CA), var=sq*(1.f/CA)-mean*mean;
    float xn=(x-mean)*rsqrtf(var+1e-5f);
    size_t base = (size_t)t*NG;
    float sc  = g_gatesP[base + (blk*6+0)*128 + c];
    float sh_ = g_gatesP[base + (blk*6+1)*128 + c];
    float tsc = g_gatesP[base + (blk*6+3)*128 + c];
    float tsh = g_gatesP[base + (blk*6+4)*128 + c];
    size_t o=(size_t)t*CA+c;
    g_aln[o] = sc*xn + sh_;
    g_tln[o] = tsc*xn + tsh;
}

// ---------------- GEMM: tf32 3x, CTA 64(M)x128(N), BK=16, double-buffered ----------------
#define A_STRIDE 40   /* 2*16 + 8 pad */
#define B_STRIDE 264  /* 2*128 + 8 pad */
#define ASZ (64*A_STRIDE)
#define BSZ (16*B_STRIDE)
#define GEMM_SMEM ((2*ASZ + 2*BSZ)*4)
__global__ __launch_bounds__(256) void gemm_kernel(
        const float* __restrict__ A, int lda, const float* __restrict__ A2,
        const float* __restrict__ Bm, const float* __restrict__ biasv, unsigned sigmask,
        const float* __restrict__ mulp, int ldmul,
        const float* __restrict__ addp, int ldadd,
        float* __restrict__ C, int M, int N, int K){
    extern __shared__ float sh[];
    int n0 = blockIdx.x*128, m0 = blockIdx.y*64;   // n fastest for L2 A-reuse
    int tid = threadIdx.x, lane = tid&31, wid = tid>>5;
    int g = lane>>2, tig = lane&3;
    int wm = (wid&1)*32, wn = (wid>>1)*32;
    float acc[2][4][4] = {};
    const int nit = K>>4;

    int ar = tid>>2, akq = tid&3;     // A: row 0..63, k-float4 0..3
    int br = tid>>5, bnq = tid&31;    // B: k rows br, br+8; n-float4 0..31
    const float* Ap  = A + (size_t)(m0+ar)*lda + akq*4;
    const float* Gp  = A2 ? A2 + (size_t)(m0+ar)*lda + akq*4 : (const float*)0;
    const float* Bp0 = Bm + (size_t)br*N + n0 + bnq*4;
    const float* Bp1 = Bm + (size_t)(br+8)*N + n0 + bnq*4;

    float4 pa, pg, pb0, pb1;
    pg = make_float4(0.f,0.f,0.f,0.f);
    pa  = *(const float4*)Ap;
    if (A2) pg = *(const float4*)Gp;
    pb0 = *(const float4*)Bp0;
    pb1 = *(const float4*)Bp1;

    // store prefetched regs into smem buffer `buf`
    auto store_tile = [&](int buf){
        float* Asm_ = sh + buf*ASZ;
        float* Bsm_ = sh + 2*ASZ + buf*BSZ;
        float4 v = pa;
        if (A2){
            v.x = v.x*sigm(v.x)*pg.x; v.y = v.y*sigm(v.y)*pg.y;
            v.z = v.z*sigm(v.z)*pg.z; v.w = v.w*sigm(v.w)*pg.w;
        }
        float2 sx=split_tf32(v.x), sy=split_tf32(v.y), sz=split_tf32(v.z), sw=split_tf32(v.w);
        float* da = &Asm_[ar*A_STRIDE + akq*8];
        ((float4*)da)[0] = make_float4(sx.x,sx.y,sy.x,sy.y);
        ((float4*)da)[1] = make_float4(sz.x,sz.y,sw.x,sw.y);

        float2 bx=split_tf32(pb0.x), by=split_tf32(pb0.y), bz=split_tf32(pb0.z), bw=split_tf32(pb0.w);
        float* db0 = &Bsm_[br*B_STRIDE + bnq*8];
        ((float4*)db0)[0] = make_float4(bx.x,bx.y,by.x,by.y);
        ((float4*)db0)[1] = make_float4(bz.x,bz.y,bw.x,bw.y);
        bx=split_tf32(pb1.x); by=split_tf32(pb1.y); bz=split_tf32(pb1.z); bw=split_tf32(pb1.w);
        float* db1 = &Bsm_[(br+8)*B_STRIDE + bnq*8];
        ((float4*)db1)[0] = make_float4(bx.x,bx.y,by.x,by.y);
        ((float4*)db1)[1] = make_float4(bz.x,bz.y,bw.x,bw.y);
    };

    store_tile(0);
    __syncthreads();

    for (int it=0; it<nit; it++){
        int cur = it&1;
        if (it+1 < nit){
            pa  = *(const float4*)(Ap + (it+1)*16);
            if (A2) pg = *(const float4*)(Gp + (it+1)*16);
            pb0 = *(const float4*)(Bp0 + (size_t)(it+1)*16*N);
            pb1 = *(const float4*)(Bp1 + (size_t)(it+1)*16*N);
        }
        const float* Ac = sh + cur*ASZ;
        const float* Bc = sh + 2*ASZ + cur*BSZ;
        #pragma unroll
        for (int ks=0; ks<16; ks+=8){
            unsigned ah[2][4], al[2][4], bh[4][2], bl[4][2];
            #pragma unroll
            for (int mt=0; mt<2; mt++){
                int row = wm + mt*16 + g;
                float2 p0 = *(const float2*)&Ac[ row   *A_STRIDE + 2*(ks+tig)  ];
                float2 p1 = *(const float2*)&Ac[(row+8)*A_STRIDE + 2*(ks+tig)  ];
                float2 p2 = *(const float2*)&Ac[ row   *A_STRIDE + 2*(ks+tig+4)];
                float2 p3 = *(const float2*)&Ac[(row+8)*A_STRIDE + 2*(ks+tig+4)];
                ah[mt][0]=__float_as_uint(p0.x); al[mt][0]=__float_as_uint(p0.y);
                ah[mt][1]=__float_as_uint(p1.x); al[mt][1]=__float_as_uint(p1.y);
                ah[mt][2]=__float_as_uint(p2.x); al[mt][2]=__float_as_uint(p2.y);
                ah[mt][3]=__float_as_uint(p3.x); al[mt][3]=__float_as_uint(p3.y);
            }
            #pragma unroll
            for (int nt=0; nt<4; nt++){
                int n = wn + nt*8 + g;
                float2 q0 = *(const float2*)&Bc[(ks+tig  )*B_STRIDE + 2*n];
                float2 q1 = *(const float2*)&Bc[(ks+tig+4)*B_STRIDE + 2*n];
                bh[nt][0]=__float_as_uint(q0.x); bl[nt][0]=__float_as_uint(q0.y);
                bh[nt][1]=__float_as_uint(q1.x); bl[nt][1]=__float_as_uint(q1.y);
            }
            #pragma unroll
            for (int mt=0; mt<2; mt++){
                #pragma unroll
                for (int nt=0; nt<4; nt++){
                    mma_tf32(acc[mt][nt], ah[mt], bh[nt]);
                    mma_tf32(acc[mt][nt], ah[mt], bl[nt]);
                    mma_tf32(acc[mt][nt], al[mt], bh[nt]);
                }
            }
        }
        if (it+1 < nit){
            store_tile(1-cur);
            __syncthreads();
        }
    }

    // epilogue
    #pragma unroll
    for (int mt=0; mt<2; mt++){
        #pragma unroll
        for (int nt=0; nt<4; nt++){
            int row0 = m0 + wm + mt*16 + g;
            int row1 = row0 + 8;
            int col  = n0 + wn + nt*8 + 2*tig;
            float b0 = biasv ? biasv[col]   : 0.f;
            float b1 = biasv ? biasv[col+1] : 0.f;
            float e0 = acc[mt][nt][0] + b0, e1 = acc[mt][nt][1] + b1;
            float e2 = acc[mt][nt][2] + b0, e3 = acc[mt][nt][3] + b1;
            if ((sigmask >> (col>>7)) & 1u){ e0=sigm(e0); e1=sigm(e1); e2=sigm(e2); e3=sigm(e3); }
            size_t o0 = (size_t)row0*N + col, o1 = (size_t)row1*N + col;
            if (mulp){
                size_t u0 = (size_t)row0*ldmul + col, u1 = (size_t)row1*ldmul + col;
                e0*=mulp[u0]; e1*=mulp[u0+1]; e2*=mulp[u1]; e3*=mulp[u1+1];
            }
            if (addp){
                size_t u0 = (size_t)row0*ldadd + col, u1 = (size_t)row1*ldadd + col;
                e0+=addp[u0]; e1+=addp[u0+1]; e2+=addp[u1]; e3+=addp[u1+1];
            }
            *(float2*)&C[o0] = make_float2(e0,e1);
            *(float2*)&C[o1] = make_float2(e2,e3);
        }
    }
}

// ---------------- K6: windowed attention, one CTA per (b, w, h) ----------------
__global__ void attn_kernel(int blk){
    __shared__ float qs[NQ*DD];       // 32x32
    __shared__ float kv[NK*33];       // 128x32 padded (K tile, later reused as V tile)
    __shared__ float lb[NQ*129];      // bias -> logits -> attn, padded rows
    int w = blockIdx.x, h = blockIdx.y, b = blockIdx.z;
    int tid = threadIdx.x;            // 256
    size_t tokbase = (size_t)b*NN + (size_t)w*NQ;
    int kstart = w*NQ - 48;           // (NK-NQ)/2 = 48
    for (int i=tid; i<NQ*DD; i+=256){
        int r=i>>5, c=i&31;
        qs[i] = g_qkvg[(tokbase+r)*512 + h*DD + c];
    }
    for (int i=tid; i<NK*DD; i+=256){
        int r=i>>5, c=i&31;
        int src = kstart + r; src = min(max(src,0), NN-1);
        kv[r*33+c] = g_qkvg[((size_t)b*NN + src)*512 + 128 + h*DD + c];
    }
    const float* plane = g_biasbuf + ((size_t)blk*HH + h)*(size_t)ROWS;
    size_t rb = (((size_t)b*WW + w)*NQ)*NK;
    for (int i=tid; i<NQ*NK; i+=256){
        int q=i>>7, k=i&127;
        lb[q*129+k] = plane[rb + i];
    }
    __syncthreads();
    {
        int qt = tid>>5, kt = tid&31;
        float acc[4][4] = {};
        #pragma unroll
        for (int d=0; d<DD; d++){
            float qa[4], kb[4];
            #pragma unroll
            for (int j=0;j<4;j++) qa[j] = qs[(qt*4+j)*DD + d];
            #pragma unroll
            for (int l=0;l<4;l++) kb[l] = kv[(kt+32*l)*33 + d];
            #pragma unroll
            for (int j=0;j<4;j++)
                #pragma unroll
                for (int l=0;l<4;l++) acc[j][l] += qa[j]*kb[l];
        }
        const float isd = 0.17677669529663687f;  // 1/sqrt(32)
        #pragma unroll
        for (int j=0;j<4;j++){
            #pragma unroll
            for (int l=0;l<4;l++){
                int q = qt*4+j, k = kt+32*l;
                int src = kstart + k;
                float v = (src>=0 && src<NN) ? acc[j][l]*isd + lb[q*129+k] : -1e9f;
                lb[q*129+k] = v;
            }
        }
    }
    __syncthreads();
    for (int i=tid; i<NK*DD; i+=256){
        int r=i>>5, c=i&31;
        int src = kstart + r; src = min(max(src,0), NN-1);
        kv[r*33+c] = g_qkvg[((size_t)b*NN + src)*512 + 256 + h*DD + c];
    }
    {
        int wid = tid>>5, lane = tid&31;
        for (int rq=0; rq<4; rq++){
            int q = wid*4 + rq;
            float m = -1e30f;
            #pragma unroll
            for (int k=lane; k<NK; k+=32) m = fmaxf(m, lb[q*129+k]);
            #pragma unroll
            for (int o=16;o;o>>=1) m = fmaxf(m, __shfl_xor_sync(0xffffffffu, m, o));
            float ssum = 0.f;
            #pragma unroll
            for (int k=lane; k<NK; k+=32){
                float e = __expf(lb[q*129+k] - m);
                lb[q*129+k] = e; ssum += e;
            }
            #pragma unroll
            for (int o=16;o;o>>=1) ssum += __shfl_xor_sync(0xffffffffu, ssum, o);
            float invs = 1.f/ssum;
            #pragma unroll
            for (int k=lane; k<NK; k+=32) lb[q*129+k] *= invs;
        }
    }
    __syncthreads();
    {
        int qp = tid>>4, dp = tid&15;
        float av[2][2] = {};
        #pragma unroll 4
        for (int k=0;k<NK;k++){
            float p0 = lb[(qp*2  )*129 + k];
            float p1 = lb[(qp*2+1)*129 + k];
            float v0 = kv[k*33 + dp];
            float v1 = kv[k*33 + dp + 16];
            av[0][0]+=p0*v0; av[0][1]+=p0*v1; av[1][0]+=p1*v0; av[1][1]+=p1*v1;
        }
        #pragma unroll
        for (int a2=0;a2<2;a2++){
            #pragma unroll
            for (int b2=0;b2<2;b2++){
                int q = qp*2+a2, d = dp+16*b2;
                float gate = g_qkvg[(tokbase+q)*512 + 384 + h*DD + d];
                g_att[(tokbase+q)*CA + h*DD + d] = gate*av[a2][b2];
            }
        }
    }
}

// ---------------- host launcher ----------------
extern "C" void kernel_launch(void* const* d_in, const int* in_sizes, int n_in,
                              void* d_out, int out_size){
    const float* q_in   = (const float*)d_in[0];
    const float* s_in   = (const float*)d_in[1];
    const float* p_in   = (const float*)d_in[2];
    const float* adaln_scale_w = (const float*)d_in[3];
    const float* adaln_scale_b = (const float*)d_in[4];
    const float* adaln_shift_w = (const float*)d_in[5];
    const float* wq = (const float*)d_in[6];
    const float* bq = (const float*)d_in[7];
    const float* wk = (const float*)d_in[8];
    const float* wv = (const float*)d_in[9];
    const float* lnz_w = (const float*)d_in[10];
    const float* lnz_b = (const float*)d_in[11];
    const float* wb_pair = (const float*)d_in[12];
    const float* wg = (const float*)d_in[13];
    const float* wo = (const float*)d_in[14];
    const float* sgate_w = (const float*)d_in[15];
    const float* sgate_b = (const float*)d_in[16];
    const float* t_scale_w = (const float*)d_in[17];
    const float* t_scale_b = (const float*)d_in[18];
    const float* t_shift_w = (const float*)d_in[19];
    const float* t_wa = (const float*)d_in[20];
    const float* t_wb = (const float*)d_in[21];
    const float* t_wo = (const float*)d_in[22];
    const float* t_sgate_w = (const float*)d_in[23];
    const float* t_sgate_b = (const float*)d_in[24];
    float* out = (float*)d_out;

    float *p_sln, *p_gatesP, *p_aln, *p_tln, *p_qkvg, *p_att, *p_ao, *p_a, *p_hid;
    float *p_wgate, *p_bgate, *p_wqkvg, *p_bqkvg, *p_whid;
    cudaGetSymbolAddress((void**)&p_sln,   g_sln);
    cudaGetSymbolAddress((void**)&p_gatesP,g_gatesP);
    cudaGetSymbolAddress((void**)&p_aln,   g_aln);
    cudaGetSymbolAddress((void**)&p_tln,   g_tln);
    cudaGetSymbolAddress((void**)&p_qkvg,  g_qkvg);
    cudaGetSymbolAddress((void**)&p_att,   g_att);
    cudaGetSymbolAddress((void**)&p_ao,    g_ao);
    cudaGetSymbolAddress((void**)&p_a,     g_a);
    cudaGetSymbolAddress((void**)&p_hid,   g_hid);
    cudaGetSymbolAddress((void**)&p_wgate, g_wgate);
    cudaGetSymbolAddress((void**)&p_bgate, g_bgate);
    cudaGetSymbolAddress((void**)&p_wqkvg, g_wqkvg);
    cudaGetSymbolAddress((void**)&p_bqkvg, g_bqkvg);
    cudaGetSymbolAddress((void**)&p_whid,  g_whid);

    cudaFuncSetAttribute(gemm_kernel, cudaFuncAttributeMaxDynamicSharedMemorySize, GEMM_SMEM);

    // stage 0: pack weights + invariants
    {
        int total = 18*CS*CA + 2*NB*CA*512 + NG + NB*512;
        pack_kernel<<<(total+255)/256,256>>>(adaln_scale_w, adaln_shift_w, sgate_w,
            t_scale_w, t_shift_w, t_sgate_w,
            adaln_scale_b, sgate_b, t_scale_b, t_sgate_b,
            wq, bq, wk, wv, wg, t_wa, t_wb);
    }
    sln_kernel<<<TT,128>>>(s_in);
    bias_kernel<<<ROWS/256,256>>>(p_in, lnz_w, lnz_b, wb_pair);
    // one big gate GEMM: [TT,2304] = sln @ Wgate
    // sigmask: col-group (128 wide) g of block i gets sigmoid for g in {0,2,3,5}
    // groups: i*6+g -> bit (i*6+g). pattern per block: 101101 -> bits 0,2,3,5
    // mask = 0b101101 repeated: blocks 0..2 -> 0x2D | 0x2D<<6 | 0x2D<<12
    gemm_kernel<<<dim3(NG/128, TT/64),256,GEMM_SMEM>>>(
        p_sln, CS, (const float*)0, p_wgate, p_bgate,
        (0x2Du) | (0x2Du<<6) | (0x2Du<<12),
        (const float*)0, 0, (const float*)0, 0, p_gatesP, TT, NG, CS);

    // stage 1: the 3 transformer blocks
    const float* acur = q_in;
    for (int i=0;i<NB;i++){
        lnmod_kernel<<<TT,128>>>(acur, i);
        // QKVG fused: [TT,512]; sigmoid only on col-group 3 (the g gate)
        gemm_kernel<<<dim3(4, TT/64),256,GEMM_SMEM>>>(
            p_aln, CA, (const float*)0, p_wqkvg + (size_t)i*CA*512, p_bqkvg + i*512, 8u,
            (const float*)0, 0, (const float*)0, 0, p_qkvg, TT, 512, CA);
        attn_kernel<<<dim3(WW,HH,Bb),256>>>(i);
        // attn_out = (att @ wo) * sgate
        gemm_kernel<<<dim3(1, TT/64),256,GEMM_SMEM>>>(
            p_att, CA, (const float*)0, wo + (size_t)i*CA*CA, (const float*)0, 0u,
            p_gatesP + (size_t)(i*6+2)*128, NG, (const float*)0, 0, p_ao, TT, CA, CA);
        // hidden: [TT,512] = tln @ (t_wa|t_wb)
        gemm_kernel<<<dim3(4, TT/64),256,GEMM_SMEM>>>(
            p_tln, CA, (const float*)0, p_whid + (size_t)i*CA*512, (const float*)0, 0u,
            (const float*)0, 0, (const float*)0, 0, p_hid, TT, 512, CA);
        // GLU + t_wo + t_sgate + residual add of attn_out
        float* dst = (i==NB-1) ? out : p_a;
        gemm_kernel<<<dim3(1, TT/64),256,GEMM_SMEM>>>(
            p_hid, 512, p_hid + 256, t_wo + (size_t)i*HID*CA, (const float*)0, 0u,
            p_gatesP + (size_t)(i*6+5)*128, NG, p_ao, CA, dst, TT, CA, HID);
        acur = p_a;
    }
    (void)in_sizes; (void)n_in; (void)out_size;
}

// round 7
// speedup vs baseline: 2.4925x; 1.3930x over previous
#include <cuda_runtime.h>
#include <cuda_bf16.h>
#include <math.h>

#define Bb  2
#define NN  8192
#define CA  128
#define CS  384
#define CZ  16
#define HH  4
#define DD  32
#define NQ  32
#define NK  128
#define NB  3
#define WW  256
#define HID 256
#define TT  (Bb*NN)          /* 16384 tokens */
#define ROWS 2097152         /* B*W*NQ*NK */
#define NG  2304             /* 18*128 packed gate width */

// ---------------- scratch (device globals; no allocation allowed) ----------------
__device__ float g_sln   [(size_t)TT*CS];
__device__ float g_gatesP[(size_t)TT*NG];        // packed gates [t][(blk*6+g)*128+c]
__device__ float g_biasbuf[(size_t)NB*HH*ROWS];  // [blk][h][row]
__device__ float g_aln[(size_t)TT*CA];
__device__ float g_tln[(size_t)TT*CA];
__device__ float g_qkvg[(size_t)TT*512];         // q|k|v|g packed
__device__ float g_att[(size_t)TT*CA];
__device__ float g_ao [(size_t)TT*CA];
__device__ float g_a  [(size_t)TT*CA];
__device__ float g_hid[(size_t)TT*512];          // ha|hb packed
// packed weights/biases (rebuilt every launch from inputs)
__device__ float g_wgate[(size_t)CS*NG];
__device__ float g_bgate[NG];
__device__ float g_wqkvg[(size_t)NB*CA*512];
__device__ float g_bqkvg[NB*512];
__device__ float g_whid [(size_t)NB*CA*512];

__device__ __forceinline__ float sigm(float x){ return 1.f/(1.f+__expf(-x)); }

// split x0,x1 into packed bf16 hi and lo words (low half = first element)
__device__ __forceinline__ void split2(float x0, float x1, unsigned &hi, unsigned &lo){
    __nv_bfloat16 h0 = __float2bfloat16(x0);
    __nv_bfloat16 h1 = __float2bfloat16(x1);
    __nv_bfloat16 l0 = __float2bfloat16(x0 - __bfloat162float(h0));
    __nv_bfloat16 l1 = __float2bfloat16(x1 - __bfloat162float(h1));
    hi = (unsigned)__bfloat16_as_ushort(h0) | ((unsigned)__bfloat16_as_ushort(h1)<<16);
    lo = (unsigned)__bfloat16_as_ushort(l0) | ((unsigned)__bfloat16_as_ushort(l1)<<16);
}

__device__ __forceinline__ void mma_bf16(float* c, const unsigned* a, const unsigned* b){
    asm volatile(
        "mma.sync.aligned.m16n8k16.row.col.f32.bf16.bf16.f32 "
        "{%0,%1,%2,%3},{%4,%5,%6,%7},{%8,%9},{%0,%1,%2,%3};"
        : "+f"(c[0]), "+f"(c[1]), "+f"(c[2]), "+f"(c[3])
        : "r"(a[0]), "r"(a[1]), "r"(a[2]), "r"(a[3]), "r"(b[0]), "r"(b[1]));
}

__device__ __forceinline__ void blockReduce2_128(float& s, float& q){
    __shared__ float sb[8];
    #pragma unroll
    for (int o=16;o;o>>=1){
        s += __shfl_xor_sync(0xffffffffu, s, o);
        q += __shfl_xor_sync(0xffffffffu, q, o);
    }
    int wid = threadIdx.x>>5;
    if ((threadIdx.x&31)==0){ sb[wid*2]=s; sb[wid*2+1]=q; }
    __syncthreads();
    s = sb[0]+sb[2]+sb[4]+sb[6];
    q = sb[1]+sb[3]+sb[5]+sb[7];
}

// ---------------- weight/bias packing (once per launch) ----------------
__global__ void pack_kernel(
    const float* __restrict__ aw,  const float* __restrict__ ashw,
    const float* __restrict__ sgw, const float* __restrict__ tsw,
    const float* __restrict__ tshw,const float* __restrict__ tsgw,
    const float* __restrict__ a_sb,const float* __restrict__ sg_b,
    const float* __restrict__ ts_b,const float* __restrict__ tsg_b,
    const float* __restrict__ wq,  const float* __restrict__ bq,
    const float* __restrict__ wk,  const float* __restrict__ wv,
    const float* __restrict__ wg,  const float* __restrict__ twa,
    const float* __restrict__ twb)
{
    int idx = blockIdx.x*256 + threadIdx.x;
    const int R1 = 18*CS*CA;
    const int R2 = NB*CA*512;
    const int R3 = NB*CA*512;
    if (idx < R1){
        int k = idx / NG, r = idx % NG;
        int gi = r >> 7, c = r & 127;
        int i = gi/6, g = gi - i*6;
        const float* src;
        switch(g){
            case 0: src = aw;  break;
            case 1: src = ashw;break;
            case 2: src = sgw; break;
            case 3: src = tsw; break;
            case 4: src = tshw;break;
            default:src = tsgw;break;
        }
        g_wgate[idx] = src[((size_t)i*CS + k)*CA + c];
        return;
    }
    idx -= R1;
    if (idx < R2){
        int r = idx % (CA*512);
        int blk = idx / (CA*512);
        int k = r >> 9, j = r & 511;
        float v;
        if (j < 128)      v = wq[((size_t)blk*CA + k)*128 + j];
        else if (j < 256) v = wk[((size_t)blk*CA + k)*128 + (j-128)];
        else if (j < 384) v = wv[((size_t)blk*CA + k)*128 + (j-256)];
        else              v = wg[((size_t)blk*CA + k)*128 + (j-384)];
        g_wqkvg[idx] = v;
        return;
    }
    idx -= R2;
    if (idx < R3){
        int r = idx % (CA*512);
        int blk = idx / (CA*512);
        int k = r >> 9, j = r & 511;
        g_whid[idx] = (j<256) ? twa[((size_t)blk*CA + k)*256 + j]
                              : twb[((size_t)blk*CA + k)*256 + (j-256)];
        return;
    }
    idx -= R3;
    if (idx < NG){
        int gi = idx >> 7, c = idx & 127;
        int i = gi/6, g = gi - i*6;
        float v = 0.f;
        if (g==0) v = a_sb[i*128+c];
        else if (g==2) v = sg_b[i*128+c];
        else if (g==3) v = ts_b[i*128+c];
        else if (g==5) v = tsg_b[i*128+c];
        g_bgate[idx] = v;
        return;
    }
    idx -= NG;
    if (idx < NB*512){
        int blk = idx >> 9, j = idx & 511;
        g_bqkvg[idx] = (j<128) ? bq[blk*128 + j] : 0.f;
    }
}

// ---------------- K1: layernorm of s (once) ----------------
__global__ void sln_kernel(const float* __restrict__ s){
    int t = blockIdx.x, tid = threadIdx.x;
    const float* row = s + (size_t)t*CS;
    float v0=row[tid], v1=row[tid+128], v2=row[tid+256];
    float su=v0+v1+v2, sq=v0*v0+v1*v1+v2*v2;
    blockReduce2_128(su,sq);
    float mean = su*(1.f/CS);
    float var  = sq*(1.f/CS) - mean*mean;
    float inv  = rsqrtf(var + 1e-5f);
    float* o = g_sln + (size_t)t*CS;
    o[tid]=(v0-mean)*inv; o[tid+128]=(v1-mean)*inv; o[tid+256]=(v2-mean)*inv;
}

// ---------------- K3: pair bias for all 3 blocks (once) ----------------
__global__ void bias_kernel(const float* __restrict__ p, const float* __restrict__ lnz_w,
                            const float* __restrict__ lnz_b, const float* __restrict__ wb){
    __shared__ float s_w[NB*CZ], s_b[NB*CZ], s_wb[NB*CZ*HH];
    int tid = threadIdx.x;
    if (tid < NB*CZ){ s_w[tid]=lnz_w[tid]; s_b[tid]=lnz_b[tid]; }
    if (tid < NB*CZ*HH) s_wb[tid]=wb[tid];
    __syncthreads();
    size_t r = (size_t)blockIdx.x*blockDim.x + tid;
    if (r >= (size_t)ROWS) return;
    const float4* p4 = (const float4*)(p + r*CZ);
    float z[16];
    float4 q0=p4[0], q1=p4[1], q2=p4[2], q3=p4[3];
    z[0]=q0.x; z[1]=q0.y; z[2]=q0.z; z[3]=q0.w;
    z[4]=q1.x; z[5]=q1.y; z[6]=q1.z; z[7]=q1.w;
    z[8]=q2.x; z[9]=q2.y; z[10]=q2.z; z[11]=q2.w;
    z[12]=q3.x; z[13]=q3.y; z[14]=q3.z; z[15]=q3.w;
    float su=0, sq=0;
    #pragma unroll
    for (int c=0;c<16;c++){ su+=z[c]; sq+=z[c]*z[c]; }
    float mean=su*(1.f/16.f), var=sq*(1.f/16.f)-mean*mean;
    float inv=rsqrtf(var+1e-5f);
    #pragma unroll
    for (int c=0;c<16;c++) z[c]=(z[c]-mean)*inv;
    #pragma unroll
    for (int i=0;i<NB;i++){
        float o0=0,o1=0,o2=0,o3=0;
        #pragma unroll
        for (int c=0;c<16;c++){
            float zz = z[c]*s_w[i*16+c] + s_b[i*16+c];
            const float* w4 = &s_wb[(i*16+c)*4];
            o0 += zz*w4[0]; o1 += zz*w4[1]; o2 += zz*w4[2]; o3 += zz*w4[3];
        }
        size_t base = ((size_t)i*HH)*ROWS + r;
        g_biasbuf[base]        = o0;
        g_biasbuf[base+ROWS]   = o1;
        g_biasbuf[base+2*(size_t)ROWS] = o2;
        g_biasbuf[base+3*(size_t)ROWS] = o3;
    }
}

// ---------------- K4: LN(a) + both modulations (per block) ----------------
__global__ void lnmod_kernel(const float* __restrict__ a, int blk){
    int t = blockIdx.x, c = threadIdx.x;
    float x = a[(size_t)t*CA + c];
    float su=x, sq=x*x;
    blockReduce2_128(su,sq);
    float mean=su*(1.f/CA), var=sq*(1.f/CA)-mean*mean;
    float xn=(x-mean)*rsqrtf(var+1e-5f);
    size_t base = (size_t)t*NG;
    float sc  = g_gatesP[base + (blk*6+0)*128 + c];
    float sh_ = g_gatesP[base + (blk*6+1)*128 + c];
    float tsc = g_gatesP[base + (blk*6+3)*128 + c];
    float tsh = g_gatesP[base + (blk*6+4)*128 + c];
    size_t o=(size_t)t*CA+c;
    g_aln[o] = sc*xn + sh_;
    g_tln[o] = tsc*xn + tsh;
}

// ---------------- GEMM: 3xBF16 (m16n8k16), CTA 64(M)x128(N), BK=16, double-buffered ----------------
// A in smem [row][k] bf16 hi/lo planes (stride AS halves);
// B in smem TRANSPOSED [n][k] bf16 hi/lo planes (stride BS halves).
#define AS_  18   /* halves per A row: 16 + 2 pad */
#define BS_  18   /* halves per B (n) row */
#define APL (64*AS_)       /* 1152 halves */
#define BPL (128*BS_)      /* 2304 halves */
#define BUFH (2*APL + 2*BPL)  /* halves per buffer: 6912 */
#define GEMM_SMEM (2*BUFH*2)  /* bytes: 27648 */
__global__ __launch_bounds__(256) void gemm_kernel(
        const float* __restrict__ A, int lda, const float* __restrict__ A2,
        const float* __restrict__ Bm, const float* __restrict__ biasv, unsigned sigmask,
        const float* __restrict__ mulp, int ldmul,
        const float* __restrict__ addp, int ldadd,
        float* __restrict__ C, int M, int N, int K){
    extern __shared__ __align__(16) unsigned short sh[];
    int n0 = blockIdx.x*128, m0 = blockIdx.y*64;
    int tid = threadIdx.x, lane = tid&31, wid = tid>>5;
    int g = lane>>2, tig = lane&3;
    int wm = (wid&1)*32, wn = (wid>>1)*32;
    float acc[2][4][4] = {};
    const int nit = K>>4;

    // A loader: row ar (0..63), k-quad akq (4 floats)
    int ar = tid>>2, akq = tid&3;
    const float* Ap = A + (size_t)(m0+ar)*lda + akq*4;
    const float* Gp = A2 ? A2 + (size_t)(m0+ar)*lda + akq*4 : (const float*)0;
    // B loader: column n (0..127), k-base bkb (8 consecutive k)
    int bn = tid&127, bkb = (tid>>7)*8;
    const float* Bp = Bm + (size_t)bkb*N + n0 + bn;

    float4 pa, pg; float pb[8];
    pg = make_float4(0.f,0.f,0.f,0.f);
    pa = *(const float4*)Ap;
    if (A2) pg = *(const float4*)Gp;
    #pragma unroll
    for (int j=0;j<8;j++) pb[j] = Bp[(size_t)j*N];

    auto store_tile = [&](int buf){
        unsigned short* base = sh + buf*BUFH;
        float4 v = pa;
        if (A2){
            v.x = v.x*sigm(v.x)*pg.x; v.y = v.y*sigm(v.y)*pg.y;
            v.z = v.z*sigm(v.z)*pg.z; v.w = v.w*sigm(v.w)*pg.w;
        }
        unsigned h01,l01,h23,l23;
        split2(v.x, v.y, h01, l01);
        split2(v.z, v.w, h23, l23);
        unsigned short* Ah = base;
        unsigned short* Al = base + APL;
        *(unsigned*)(Ah + ar*AS_ + akq*4)     = h01;
        *(unsigned*)(Ah + ar*AS_ + akq*4 + 2) = h23;
        *(unsigned*)(Al + ar*AS_ + akq*4)     = l01;
        *(unsigned*)(Al + ar*AS_ + akq*4 + 2) = l23;
        unsigned short* Bh = base + 2*APL;
        unsigned short* Bl = Bh + BPL;
        #pragma unroll
        for (int j=0;j<4;j++){
            unsigned hu, lu;
            split2(pb[2*j], pb[2*j+1], hu, lu);
            *(unsigned*)(Bh + bn*BS_ + bkb + 2*j) = hu;
            *(unsigned*)(Bl + bn*BS_ + bkb + 2*j) = lu;
        }
    };

    store_tile(0);
    __syncthreads();

    for (int it=0; it<nit; it++){
        int cur = it&1;
        if (it+1 < nit){
            pa = *(const float4*)(Ap + (it+1)*16);
            if (A2) pg = *(const float4*)(Gp + (it+1)*16);
            #pragma unroll
            for (int j=0;j<8;j++) pb[j] = Bp[(size_t)((it+1)*16 + j)*N];
        }
        const unsigned short* base = sh + cur*BUFH;
        const unsigned short* Ah = base;
        const unsigned short* Al = base + APL;
        const unsigned short* Bh = base + 2*APL;
        const unsigned short* Bl = Bh + BPL;

        unsigned ah[2][4], alo[2][4], bh[4][2], blo[4][2];
        #pragma unroll
        for (int mt=0; mt<2; mt++){
            int row = wm + mt*16 + g;
            ah[mt][0] = *(const unsigned*)(Ah +  row   *AS_ + 2*tig);
            ah[mt][1] = *(const unsigned*)(Ah + (row+8)*AS_ + 2*tig);
            ah[mt][2] = *(const unsigned*)(Ah +  row   *AS_ + 2*tig + 8);
            ah[mt][3] = *(const unsigned*)(Ah + (row+8)*AS_ + 2*tig + 8);
            alo[mt][0] = *(const unsigned*)(Al +  row   *AS_ + 2*tig);
            alo[mt][1] = *(const unsigned*)(Al + (row+8)*AS_ + 2*tig);
            alo[mt][2] = *(const unsigned*)(Al +  row   *AS_ + 2*tig + 8);
            alo[mt][3] = *(const unsigned*)(Al + (row+8)*AS_ + 2*tig + 8);
        }
        #pragma unroll
        for (int nt=0; nt<4; nt++){
            int n = wn + nt*8 + g;
            bh[nt][0]  = *(const unsigned*)(Bh + n*BS_ + 2*tig);
            bh[nt][1]  = *(const unsigned*)(Bh + n*BS_ + 2*tig + 8);
            blo[nt][0] = *(const unsigned*)(Bl + n*BS_ + 2*tig);
            blo[nt][1] = *(const unsigned*)(Bl + n*BS_ + 2*tig + 8);
        }
        #pragma unroll
        for (int mt=0; mt<2; mt++){
            #pragma unroll
            for (int nt=0; nt<4; nt++){
                mma_bf16(acc[mt][nt], ah[mt],  bh[nt]);
                mma_bf16(acc[mt][nt], ah[mt],  blo[nt]);
                mma_bf16(acc[mt][nt], alo[mt], bh[nt]);
            }
        }
        if (it+1 < nit){
            store_tile(1-cur);
        }
        __syncthreads();
    }

    // epilogue
    #pragma unroll
    for (int mt=0; mt<2; mt++){
        #pragma unroll
        for (int nt=0; nt<4; nt++){
            int row0 = m0 + wm + mt*16 + g;
            int row1 = row0 + 8;
            int col  = n0 + wn + nt*8 + 2*tig;
            float b0 = biasv ? biasv[col]   : 0.f;
            float b1 = biasv ? biasv[col+1] : 0.f;
            float e0 = acc[mt][nt][0] + b0, e1 = acc[mt][nt][1] + b1;
            float e2 = acc[mt][nt][2] + b0, e3 = acc[mt][nt][3] + b1;
            if ((sigmask >> (col>>7)) & 1u){ e0=sigm(e0); e1=sigm(e1); e2=sigm(e2); e3=sigm(e3); }
            size_t o0 = (size_t)row0*N + col, o1 = (size_t)row1*N + col;
            if (mulp){
                size_t u0 = (size_t)row0*ldmul + col, u1 = (size_t)row1*ldmul + col;
                e0*=mulp[u0]; e1*=mulp[u0+1]; e2*=mulp[u1]; e3*=mulp[u1+1];
            }
            if (addp){
                size_t u0 = (size_t)row0*ldadd + col, u1 = (size_t)row1*ldadd + col;
                e0+=addp[u0]; e1+=addp[u0+1]; e2+=addp[u1]; e3+=addp[u1+1];
            }
            *(float2*)&C[o0] = make_float2(e0,e1);
            *(float2*)&C[o1] = make_float2(e2,e3);
        }
    }
}

// ---------------- K6: windowed attention, one CTA per (b, w, h) ----------------
__global__ void attn_kernel(int blk){
    __shared__ float qs[NQ*DD];
    __shared__ float kv[NK*33];
    __shared__ float lb[NQ*129];
    int w = blockIdx.x, h = blockIdx.y, b = blockIdx.z;
    int tid = threadIdx.x;
    size_t tokbase = (size_t)b*NN + (size_t)w*NQ;
    int kstart = w*NQ - 48;
    for (int i=tid; i<NQ*DD; i+=256){
        int r=i>>5, c=i&31;
        qs[i] = g_qkvg[(tokbase+r)*512 + h*DD + c];
    }
    for (int i=tid; i<NK*DD; i+=256){
        int r=i>>5, c=i&31;
        int src = kstart + r; src = min(max(src,0), NN-1);
        kv[r*33+c] = g_qkvg[((size_t)b*NN + src)*512 + 128 + h*DD + c];
    }
    const float* plane = g_biasbuf + ((size_t)blk*HH + h)*(size_t)ROWS;
    size_t rb = (((size_t)b*WW + w)*NQ)*NK;
    for (int i=tid; i<NQ*NK; i+=256){
        int q=i>>7, k=i&127;
        lb[q*129+k] = plane[rb + i];
    }
    __syncthreads();
    {
        int qt = tid>>5, kt = tid&31;
        float acc[4][4] = {};
        #pragma unroll
        for (int d=0; d<DD; d++){
            float qa[4], kb[4];
            #pragma unroll
            for (int j=0;j<4;j++) qa[j] = qs[(qt*4+j)*DD + d];
            #pragma unroll
            for (int l=0;l<4;l++) kb[l] = kv[(kt+32*l)*33 + d];
            #pragma unroll
            for (int j=0;j<4;j++)
                #pragma unroll
                for (int l=0;l<4;l++) acc[j][l] += qa[j]*kb[l];
        }
        const float isd = 0.17677669529663687f;
        #pragma unroll
        for (int j=0;j<4;j++){
            #pragma unroll
            for (int l=0;l<4;l++){
                int q = qt*4+j, k = kt+32*l;
                int src = kstart + k;
                float v = (src>=0 && src<NN) ? acc[j][l]*isd + lb[q*129+k] : -1e9f;
                lb[q*129+k] = v;
            }
        }
    }
    __syncthreads();
    for (int i=tid; i<NK*DD; i+=256){
        int r=i>>5, c=i&31;
        int src = kstart + r; src = min(max(src,0), NN-1);
        kv[r*33+c] = g_qkvg[((size_t)b*NN + src)*512 + 256 + h*DD + c];
    }
    {
        int wid = tid>>5, lane = tid&31;
        for (int rq=0; rq<4; rq++){
            int q = wid*4 + rq;
            float m = -1e30f;
            #pragma unroll
            for (int k=lane; k<NK; k+=32) m = fmaxf(m, lb[q*129+k]);
            #pragma unroll
            for (int o=16;o;o>>=1) m = fmaxf(m, __shfl_xor_sync(0xffffffffu, m, o));
            float ssum = 0.f;
            #pragma unroll
            for (int k=lane; k<NK; k+=32){
                float e = __expf(lb[q*129+k] - m);
                lb[q*129+k] = e; ssum += e;
            }
            #pragma unroll
            for (int o=16;o;o>>=1) ssum += __shfl_xor_sync(0xffffffffu, ssum, o);
            float invs = 1.f/ssum;
            #pragma unroll
            for (int k=lane; k<NK; k+=32) lb[q*129+k] *= invs;
        }
    }
    __syncthreads();
    {
        int qp = tid>>4, dp = tid&15;
        float av[2][2] = {};
        #pragma unroll 4
        for (int k=0;k<NK;k++){
            float p0 = lb[(qp*2  )*129 + k];
            float p1 = lb[(qp*2+1)*129 + k];
            float v0 = kv[k*33 + dp];
            float v1 = kv[k*33 + dp + 16];
            av[0][0]+=p0*v0; av[0][1]+=p0*v1; av[1][0]+=p1*v0; av[1][1]+=p1*v1;
        }
        #pragma unroll
        for (int a2=0;a2<2;a2++){
            #pragma unroll
            for (int b2=0;b2<2;b2++){
                int q = qp*2+a2, d = dp+16*b2;
                float gate = g_qkvg[(tokbase+q)*512 + 384 + h*DD + d];
                g_att[(tokbase+q)*CA + h*DD + d] = gate*av[a2][b2];
            }
        }
    }
}

// ---------------- host launcher ----------------
extern "C" void kernel_launch(void* const* d_in, const int* in_sizes, int n_in,
                              void* d_out, int out_size){
    const float* q_in   = (const float*)d_in[0];
    const float* s_in   = (const float*)d_in[1];
    const float* p_in   = (const float*)d_in[2];
    const float* adaln_scale_w = (const float*)d_in[3];
    const float* adaln_scale_b = (const float*)d_in[4];
    const float* adaln_shift_w = (const float*)d_in[5];
    const float* wq = (const float*)d_in[6];
    const float* bq = (const float*)d_in[7];
    const float* wk = (const float*)d_in[8];
    const float* wv = (const float*)d_in[9];
    const float* lnz_w = (const float*)d_in[10];
    const float* lnz_b = (const float*)d_in[11];
    const float* wb_pair = (const float*)d_in[12];
    const float* wg = (const float*)d_in[13];
    const float* wo = (const float*)d_in[14];
    const float* sgate_w = (const float*)d_in[15];
    const float* sgate_b = (const float*)d_in[16];
    const float* t_scale_w = (const float*)d_in[17];
    const float* t_scale_b = (const float*)d_in[18];
    const float* t_shift_w = (const float*)d_in[19];
    const float* t_wa = (const float*)d_in[20];
    const float* t_wb = (const float*)d_in[21];
    const float* t_wo = (const float*)d_in[22];
    const float* t_sgate_w = (const float*)d_in[23];
    const float* t_sgate_b = (const float*)d_in[24];
    float* out = (float*)d_out;

    float *p_sln, *p_gatesP, *p_aln, *p_tln, *p_qkvg, *p_att, *p_ao, *p_a, *p_hid;
    float *p_wgate, *p_bgate, *p_wqkvg, *p_bqkvg, *p_whid;
    cudaGetSymbolAddress((void**)&p_sln,   g_sln);
    cudaGetSymbolAddress((void**)&p_gatesP,g_gatesP);
    cudaGetSymbolAddress((void**)&p_aln,   g_aln);
    cudaGetSymbolAddress((void**)&p_tln,   g_tln);
    cudaGetSymbolAddress((void**)&p_qkvg,  g_qkvg);
    cudaGetSymbolAddress((void**)&p_att,   g_att);
    cudaGetSymbolAddress((void**)&p_ao,    g_ao);
    cudaGetSymbolAddress((void**)&p_a,     g_a);
    cudaGetSymbolAddress((void**)&p_hid,   g_hid);
    cudaGetSymbolAddress((void**)&p_wgate, g_wgate);
    cudaGetSymbolAddress((void**)&p_bgate, g_bgate);
    cudaGetSymbolAddress((void**)&p_wqkvg, g_wqkvg);
    cudaGetSymbolAddress((void**)&p_bqkvg, g_bqkvg);
    cudaGetSymbolAddress((void**)&p_whid,  g_whid);

    cudaFuncSetAttribute(gemm_kernel, cudaFuncAttributeMaxDynamicSharedMemorySize, GEMM_SMEM);

    // stage 0: pack weights + invariants
    {
        int total = 18*CS*CA + 2*NB*CA*512 + NG + NB*512;
        pack_kernel<<<(total+255)/256,256>>>(adaln_scale_w, adaln_shift_w, sgate_w,
            t_scale_w, t_shift_w, t_sgate_w,
            adaln_scale_b, sgate_b, t_scale_b, t_sgate_b,
            wq, bq, wk, wv, wg, t_wa, t_wb);
    }
    sln_kernel<<<TT,128>>>(s_in);
    bias_kernel<<<ROWS/256,256>>>(p_in, lnz_w, lnz_b, wb_pair);
    // one big gate GEMM: [TT,2304] = sln @ Wgate; sigmoid pattern per block: bits {0,2,3,5}
    gemm_kernel<<<dim3(NG/128, TT/64),256,GEMM_SMEM>>>(
        p_sln, CS, (const float*)0, p_wgate, p_bgate,
        (0x2Du) | (0x2Du<<6) | (0x2Du<<12),
        (const float*)0, 0, (const float*)0, 0, p_gatesP, TT, NG, CS);

    // stage 1: the 3 transformer blocks
    const float* acur = q_in;
    for (int i=0;i<NB;i++){
        lnmod_kernel<<<TT,128>>>(acur, i);
        gemm_kernel<<<dim3(4, TT/64),256,GEMM_SMEM>>>(
            p_aln, CA, (const float*)0, p_wqkvg + (size_t)i*CA*512, p_bqkvg + i*512, 8u,
            (const float*)0, 0, (const float*)0, 0, p_qkvg, TT, 512, CA);
        attn_kernel<<<dim3(WW,HH,Bb),256>>>(i);
        gemm_kernel<<<dim3(1, TT/64),256,GEMM_SMEM>>>(
            p_att, CA, (const float*)0, wo + (size_t)i*CA*CA, (const float*)0, 0u,
            p_gatesP + (size_t)(i*6+2)*128, NG, (const float*)0, 0, p_ao, TT, CA, CA);
        gemm_kernel<<<dim3(4, TT/64),256,GEMM_SMEM>>>(
            p_tln, CA, (const float*)0, p_whid + (size_t)i*CA*512, (const float*)0, 0u,
            (const float*)0, 0, (const float*)0, 0, p_hid, TT, 512, CA);
        float* dst = (i==NB-1) ? out : p_a;
        gemm_kernel<<<dim3(1, TT/64),256,GEMM_SMEM>>>(
            p_hid, 512, p_hid + 256, t_wo + (size_t)i*HID*CA, (const float*)0, 0u,
            p_gatesP + (size_t)(i*6+5)*128, NG, p_ao, CA, dst, TT, CA, HID);
        acur = p_a;
    }
    (void)in_sizes; (void)n_in; (void)out_size;
}